// round 2
// baseline (speedup 1.0000x reference)
#include <cuda_runtime.h>
#include <cuda_bf16.h>

// Problem constants (fixed shapes): B=4, C=64, H=W=128, O=64, K=3
#define BB 4
#define CC 64
#define HH 128
#define WW 128
#define OO 64
#define HWP (HH*WW)          // 16384
#define NPIX (BB*HWP)        // 65536

typedef unsigned long long u64;

// ---------------- scratch (static device globals; no allocation) ----------------
__device__ float  g_xh[(size_t)NPIX * CC];       // x in NHWC: [b][h][w][c]   16 MB
__device__ float4 g_smp[(size_t)NPIX * 9];       // per (pixel, tap): ys, xs, mask  9.4 MB
__device__ float  g_raw[(size_t)NPIX * OO];      // pre-BN conv output, [pix][o]    16 MB
__device__ float  g_wt[9 * CC * OO];             // main weights, [k][c][o]
__device__ float  g_owt[576 * 28];               // offset weights, [c*9+kk][oc(pad to 28)]
__device__ float  g_psum[256 * OO];              // BN partial sums
__device__ float  g_psq[256 * OO];               // BN partial sumsq
__device__ float  g_scale[OO];
__device__ float  g_shift[OO];

// ---------------- packed f32x2 helpers (Blackwell FFMA2) ----------------
__device__ __forceinline__ void ffma2(u64& c, u64 a, u64 b) {
    asm("fma.rn.f32x2 %0, %1, %2, %0;" : "+l"(c) : "l"(a), "l"(b));
}
__device__ __forceinline__ u64 pack2(float v) {
    u64 r; asm("mov.b64 %0, {%1, %1};" : "=l"(r) : "f"(v)); return r;
}
__device__ __forceinline__ u64 pack2f(float a, float b) {
    u64 r; asm("mov.b64 %0, {%1, %2};" : "=l"(r) : "f"(a), "f"(b)); return r;
}
__device__ __forceinline__ float2 unpack2(u64 v) {
    float2 f; asm("mov.b64 {%0, %1}, %2;" : "=f"(f.x), "=f"(f.y) : "l"(v)); return f;
}

// ---------------- K0: NCHW -> NHWC transpose ----------------
__global__ void k_transpose(const float* __restrict__ x) {
    __shared__ float t[32][33];
    int b  = blockIdx.z;
    int c0 = blockIdx.y * 32;
    int p0 = blockIdx.x * 32;
    int tx = threadIdx.x, ty = threadIdx.y;
    #pragma unroll
    for (int j = 0; j < 4; j++) {
        int c = c0 + ty + j * 8;
        t[ty + j * 8][tx] = x[((size_t)(b * CC + c)) * HWP + p0 + tx];
    }
    __syncthreads();
    #pragma unroll
    for (int j = 0; j < 4; j++) {
        int p = p0 + ty + j * 8;
        g_xh[((size_t)(b * HWP + p)) * CC + c0 + tx] = t[tx][ty + j * 8];
    }
}

// ---------------- Kprep: weight relayouts ----------------
__global__ void k_prep(const float* __restrict__ wmain, const float* __restrict__ ow) {
    int i = blockIdx.x * 256 + threadIdx.x;
    if (i < 9 * CC * OO) {
        int k = i / (CC * OO);
        int r = i % (CC * OO);
        int c = r >> 6, o = r & 63;
        g_wt[i] = wmain[o * 576 + c * 9 + k];   // weight[o][c][ky][kx]
    }
    if (i < 576 * 28) {
        int t = i / 28, oc = i % 28;            // t = c*9 + kk
        g_owt[i] = (oc < 27) ? ow[oc * 576 + t] : 0.0f;
    }
}

// ---------------- K1: offset conv -> sample coords + mask ----------------
// block = 128 threads (one row), grid = B*H
__global__ __launch_bounds__(128) void k_offset(const float* __restrict__ ob) {
    extern __shared__ float ws[];   // [576][28]
    int bh = blockIdx.x;
    int b = bh >> 7, h = bh & 127, w = threadIdx.x;
    for (int i = threadIdx.x; i < 576 * 28; i += 128) ws[i] = g_owt[i];
    __syncthreads();

    u64 acc[14];
    #pragma unroll
    for (int j = 0; j < 14; j++) {
        float lo = (2 * j < 27) ? ob[2 * j] : 0.0f;
        float hi = (2 * j + 1 < 27) ? ob[2 * j + 1] : 0.0f;
        acc[j] = pack2f(lo, hi);
    }

    const float* xb = g_xh + (size_t)(b << 14) * CC;

    #pragma unroll 1
    for (int c4 = 0; c4 < 16; c4++) {
        float4 tap[9];
        #pragma unroll
        for (int dy = 0; dy < 3; dy++)
        #pragma unroll
        for (int dx = 0; dx < 3; dx++) {
            int y = h + dy - 1, x = w + dx - 1;
            bool v = ((unsigned)y < 128u) && ((unsigned)x < 128u);
            tap[dy * 3 + dx] = v ? *(const float4*)(xb + ((y << 7) + x) * CC + c4 * 4)
                                 : make_float4(0.f, 0.f, 0.f, 0.f);
        }
        #pragma unroll
        for (int j = 0; j < 4; j++) {
            int cc = c4 * 4 + j;
            #pragma unroll
            for (int kk = 0; kk < 9; kk++) {
                float v = (j == 0) ? tap[kk].x : (j == 1) ? tap[kk].y
                        : (j == 2) ? tap[kk].z : tap[kk].w;
                u64 vv = pack2(v);
                const ulonglong2* wr = (const ulonglong2*)&ws[(cc * 9 + kk) * 28];
                #pragma unroll
                for (int q = 0; q < 7; q++) {
                    ulonglong2 wq = wr[q];
                    ffma2(acc[2 * q],     vv, wq.x);
                    ffma2(acc[2 * q + 1], vv, wq.y);
                }
            }
        }
    }

    float a[28];
    #pragma unroll
    for (int j = 0; j < 14; j++) {
        float2 f = unpack2(acc[j]);
        a[2 * j] = f.x; a[2 * j + 1] = f.y;
    }
    int pix = (b << 14) + (h << 7) + w;
    #pragma unroll
    for (int k = 0; k < 9; k++) {
        float ys = (float)(h - 1) + (float)(k / 3) + a[2 * k];
        float xs = (float)(w - 1) + (float)(k % 3) + a[2 * k + 1];
        float mk = 1.0f / (1.0f + expf(-a[18 + k]));
        g_smp[(size_t)pix * 9 + k] = make_float4(ys, xs, mk, 0.0f);
    }
}

// ---------------- K2: gather + main conv (64 outputs per thread, FFMA2) ----------------
__global__ __launch_bounds__(128) void k_main() {
    __shared__ __align__(16) float wsh[CC * OO];   // [c][o] for current tap, 16 KB
    int t = threadIdx.x;
    int pix = blockIdx.x * 128 + t;
    int b = pix >> 14;
    const float* xb = g_xh + (size_t)(b << 14) * CC;

    u64 acc[32];
    #pragma unroll
    for (int i = 0; i < 32; i++) acc[i] = 0ull;   // packed {0.f,0.f}

    #pragma unroll 1
    for (int k = 0; k < 9; k++) {
        __syncthreads();
        for (int i = t; i < CC * OO; i += 128) wsh[i] = g_wt[k * (CC * OO) + i];
        __syncthreads();

        float4 s = g_smp[(size_t)pix * 9 + k];
        float y0f = floorf(s.x), x0f = floorf(s.y);
        float fy = s.x - y0f, fx = s.y - x0f;
        int y0 = (int)y0f, x0 = (int)x0f;
        float m = s.z;
        float gy = 1.0f - fy, gx = 1.0f - fx;
        bool vy0 = ((unsigned)y0 < 128u), vy1 = ((unsigned)(y0 + 1) < 128u);
        bool vx0 = ((unsigned)x0 < 128u), vx1 = ((unsigned)(x0 + 1) < 128u);
        float w00 = (vy0 && vx0) ? gy * gx * m : 0.0f;
        float w01 = (vy0 && vx1) ? gy * fx * m : 0.0f;
        float w10 = (vy1 && vx0) ? fy * gx * m : 0.0f;
        float w11 = (vy1 && vx1) ? fy * fx * m : 0.0f;
        int r0 = (vy0 ? y0 : 0) << 7;
        int r1 = (vy1 ? (y0 + 1) : 0) << 7;
        int cA = vx0 ? x0 : 0;
        int cBx = vx1 ? (x0 + 1) : 0;
        int o00 = (r0 + cA) * CC, o01 = (r0 + cBx) * CC;
        int o10 = (r1 + cA) * CC, o11 = (r1 + cBx) * CC;

        #pragma unroll 1
        for (int c4 = 0; c4 < 16; c4++) {
            int cb = c4 * 4;
            float4 a00 = *(const float4*)(xb + o00 + cb);
            float4 a01 = *(const float4*)(xb + o01 + cb);
            float4 a10 = *(const float4*)(xb + o10 + cb);
            float4 a11 = *(const float4*)(xb + o11 + cb);
            float4 V;
            V.x = fmaf(w00, a00.x, fmaf(w01, a01.x, fmaf(w10, a10.x, w11 * a11.x)));
            V.y = fmaf(w00, a00.y, fmaf(w01, a01.y, fmaf(w10, a10.y, w11 * a11.y)));
            V.z = fmaf(w00, a00.z, fmaf(w01, a01.z, fmaf(w10, a10.z, w11 * a11.z)));
            V.w = fmaf(w00, a00.w, fmaf(w01, a01.w, fmaf(w10, a10.w, w11 * a11.w)));

            #pragma unroll
            for (int j = 0; j < 4; j++) {
                float v = (j == 0) ? V.x : (j == 1) ? V.y : (j == 2) ? V.z : V.w;
                u64 vv = pack2(v);
                const ulonglong2* wr = (const ulonglong2*)&wsh[(cb + j) << 6];
                #pragma unroll
                for (int q = 0; q < 16; q++) {
                    ulonglong2 wq = wr[q];
                    ffma2(acc[2 * q],     vv, wq.x);
                    ffma2(acc[2 * q + 1], vv, wq.y);
                }
            }
        }
    }

    float* op = g_raw + (size_t)pix * OO;
    #pragma unroll
    for (int q = 0; q < 16; q++) {
        float2 a = unpack2(acc[2 * q]);
        float2 c = unpack2(acc[2 * q + 1]);
        *(float4*)(op + q * 4) = make_float4(a.x, a.y, c.x, c.y);
    }
}

// ---------------- K3a: per-block BN partial stats (deterministic) ----------------
__global__ void k_stats1() {
    __shared__ float ss[256], sq[256];
    int t = threadIdx.x;
    size_t base = (size_t)blockIdx.x * 256 * OO;   // 256 pixels * 64 ch
    float s = 0.0f, q = 0.0f;
    #pragma unroll 4
    for (int i = 0; i < 64; i++) {
        float v = g_raw[base + (size_t)i * 256 + t];
        s += v; q += v * v;
    }
    ss[t] = s; sq[t] = q;
    __syncthreads();
    if (t < 64) {
        float S = ss[t] + ss[t + 64] + ss[t + 128] + ss[t + 192];
        float Q = sq[t] + sq[t + 64] + sq[t + 128] + sq[t + 192];
        g_psum[blockIdx.x * 64 + t] = S;
        g_psq[blockIdx.x * 64 + t]  = Q;
    }
}

// ---------------- K3b: finalize stats -> scale/shift ----------------
__global__ void k_stats2(const float* __restrict__ gamma, const float* __restrict__ beta) {
    __shared__ float ss[256], sq[256];
    int ch = blockIdx.x, t = threadIdx.x;
    ss[t] = g_psum[t * 64 + ch];
    sq[t] = g_psq[t * 64 + ch];
    __syncthreads();
    for (int s = 128; s > 0; s >>= 1) {
        if (t < s) { ss[t] += ss[t + s]; sq[t] += sq[t + s]; }
        __syncthreads();
    }
    if (t == 0) {
        const float inv_n = 1.0f / (float)NPIX;
        float mean = ss[0] * inv_n;
        float var  = sq[0] * inv_n - mean * mean;
        float inv  = rsqrtf(var + 1e-5f);
        float sc   = gamma[ch] * inv;
        g_scale[ch] = sc;
        g_shift[ch] = beta[ch] - mean * sc;
        // conv bias cancels exactly inside batch-norm (per-channel constant)
    }
}

// ---------------- K4: BN + ReLU + NHWC->NCHW ----------------
__global__ void k_bnout(float* __restrict__ out) {
    __shared__ float s[64][65];
    __shared__ float scs[64], shs[64];
    int t = threadIdx.x;
    if (t < 64) { scs[t] = g_scale[t]; shs[t] = g_shift[t]; }
    __syncthreads();
    int pix0 = blockIdx.x * 64;
    int b = pix0 >> 14;
    int pl = pix0 & 16383;
    #pragma unroll
    for (int j = 0; j < 4; j++) {
        int idx = t + j * 256;
        int p = idx >> 4;      // 0..63 local pixel
        int q = idx & 15;      // float4 group of channels
        float4 v = *(const float4*)(g_raw + (size_t)(pix0 + p) * OO + q * 4);
        int c = q * 4;
        s[c + 0][p] = fmaxf(fmaf(v.x, scs[c + 0], shs[c + 0]), 0.0f);
        s[c + 1][p] = fmaxf(fmaf(v.y, scs[c + 1], shs[c + 1]), 0.0f);
        s[c + 2][p] = fmaxf(fmaf(v.z, scs[c + 2], shs[c + 2]), 0.0f);
        s[c + 3][p] = fmaxf(fmaf(v.w, scs[c + 3], shs[c + 3]), 0.0f);
    }
    __syncthreads();
    #pragma unroll
    for (int j = 0; j < 4; j++) {
        int idx = t + j * 256;
        int o = idx >> 4;
        int q = idx & 15;
        float4 r = make_float4(s[o][q * 4], s[o][q * 4 + 1], s[o][q * 4 + 2], s[o][q * 4 + 3]);
        *(float4*)(out + (size_t)(b * OO + o) * HWP + pl + q * 4) = r;
    }
}

// ---------------- launch ----------------
extern "C" void kernel_launch(void* const* d_in, const int* in_sizes, int n_in,
                              void* d_out, int out_size) {
    const float* x     = (const float*)d_in[0];
    const float* ow    = (const float*)d_in[1];
    const float* ob    = (const float*)d_in[2];
    const float* wt    = (const float*)d_in[3];
    // d_in[4] = bias: cancels exactly in batch norm, unused
    const float* gamma = (const float*)d_in[5];
    const float* beta  = (const float*)d_in[6];
    float* out = (float*)d_out;

    cudaFuncSetAttribute(k_offset, cudaFuncAttributeMaxDynamicSharedMemorySize, 576 * 28 * 4);

    k_transpose<<<dim3(HWP / 32, CC / 32, BB), dim3(32, 8)>>>(x);
    k_prep<<<(9 * CC * OO + 255) / 256, 256>>>(wt, ow);
    k_offset<<<BB * HH, 128, 576 * 28 * 4>>>(ob);
    k_main<<<NPIX / 128, 128>>>();
    k_stats1<<<256, 256>>>();
    k_stats2<<<64, 256>>>(gamma, beta);
    k_bnout<<<NPIX / 64, 256>>>(out);
}

// round 3
// speedup vs baseline: 1.3491x; 1.3491x over previous
#include <cuda_runtime.h>
#include <cuda_bf16.h>

// Problem constants (fixed shapes): B=4, C=64, H=W=128, O=64, K=3
#define BB 4
#define CC 64
#define HH 128
#define WW 128
#define OO 64
#define HWP (HH*WW)          // 16384
#define NPIX (BB*HWP)        // 65536

typedef unsigned long long u64;

// ---------------- scratch (static device globals; no allocation) ----------------
__device__ float  g_xh[(size_t)NPIX * CC];       // x in NHWC: [b][h][w][c]   16 MB
__device__ float4 g_smp[(size_t)9 * NPIX];       // per (tap, pixel): ys, xs, mask  9.4 MB
__device__ float  g_raw[(size_t)NPIX * OO];      // pre-BN conv output, [pix][o]    16 MB
__device__ float  g_wt[9 * CC * OO];             // main weights, [k][c][o]
__device__ float  g_owt[576 * 28];               // offset weights, [c*9+kk][oc(pad to 28)]
__device__ float  g_psum[256 * OO];              // BN partial sums
__device__ float  g_psq[256 * OO];               // BN partial sumsq
__device__ float  g_scale[OO];
__device__ float  g_shift[OO];

// ---------------- packed f32x2 helpers (Blackwell FFMA2) ----------------
__device__ __forceinline__ void ffma2(u64& c, u64 a, u64 b) {
    asm("fma.rn.f32x2 %0, %1, %2, %0;" : "+l"(c) : "l"(a), "l"(b));
}
__device__ __forceinline__ u64 pack2(float v) {
    u64 r; asm("mov.b64 %0, {%1, %1};" : "=l"(r) : "f"(v)); return r;
}
__device__ __forceinline__ u64 pack2f(float a, float b) {
    u64 r; asm("mov.b64 %0, {%1, %2};" : "=l"(r) : "f"(a), "f"(b)); return r;
}
__device__ __forceinline__ float2 unpack2(u64 v) {
    float2 f; asm("mov.b64 {%0, %1}, %2;" : "=f"(f.x), "=f"(f.y) : "l"(v)); return f;
}

// ---------------- K0: NCHW -> NHWC transpose ----------------
__global__ void k_transpose(const float* __restrict__ x) {
    __shared__ float t[32][33];
    int b  = blockIdx.z;
    int c0 = blockIdx.y * 32;
    int p0 = blockIdx.x * 32;
    int tx = threadIdx.x, ty = threadIdx.y;
    #pragma unroll
    for (int j = 0; j < 4; j++) {
        int c = c0 + ty + j * 8;
        t[ty + j * 8][tx] = x[((size_t)(b * CC + c)) * HWP + p0 + tx];
    }
    __syncthreads();
    #pragma unroll
    for (int j = 0; j < 4; j++) {
        int p = p0 + ty + j * 8;
        g_xh[((size_t)(b * HWP + p)) * CC + c0 + tx] = t[tx][ty + j * 8];
    }
}

// ---------------- Kprep: weight relayouts ----------------
__global__ void k_prep(const float* __restrict__ wmain, const float* __restrict__ ow) {
    int i = blockIdx.x * 256 + threadIdx.x;
    if (i < 9 * CC * OO) {
        int k = i / (CC * OO);
        int r = i % (CC * OO);
        int c = r >> 6, o = r & 63;
        g_wt[i] = wmain[o * 576 + c * 9 + k];   // weight[o][c][ky][kx]
    }
    if (i < 576 * 28) {
        int t = i / 28, oc = i % 28;            // t = c*9 + kk
        g_owt[i] = (oc < 27) ? ow[oc * 576 + t] : 0.0f;
    }
}

// ---------------- K1: offset conv -> sample coords + mask ----------------
// block = 128 threads = 2 rows, each thread handles 2 ADJACENT pixels (w0, w0+1)
// so every weight LDS.128 feeds 4 FFMA2 instead of 2.
__global__ __launch_bounds__(128) void k_offset(const float* __restrict__ ob) {
    extern __shared__ float ws[];   // [576][28]
    int blk = blockIdx.x;           // 0..255
    int t = threadIdx.x;
    int b = blk >> 6;
    int h = ((blk & 63) << 1) + (t >> 6);
    int w0 = (t & 63) << 1;         // this thread: pixels (h,w0) and (h,w0+1)

    for (int i = t; i < 576 * 28; i += 128) ws[i] = g_owt[i];
    __syncthreads();

    u64 acc[28];                    // [0..13]=pixel0, [14..27]=pixel1
    #pragma unroll
    for (int j = 0; j < 14; j++) {
        float lo = (2 * j < 27) ? ob[2 * j] : 0.0f;
        float hi = (2 * j + 1 < 27) ? ob[2 * j + 1] : 0.0f;
        u64 v = pack2f(lo, hi);
        acc[j] = v; acc[14 + j] = v;
    }

    const float* xb = g_xh + (size_t)(b << 14) * CC;

    #pragma unroll 1
    for (int c4 = 0; c4 < 16; c4++) {
        // 3 rows x 4 cols window covers both pixels' 3x3 taps
        float4 tap[3][4];
        #pragma unroll
        for (int dy = 0; dy < 3; dy++)
        #pragma unroll
        for (int dx = 0; dx < 4; dx++) {
            int y = h + dy - 1, x = w0 + dx - 1;
            bool v = ((unsigned)y < 128u) && ((unsigned)x < 128u);
            tap[dy][dx] = v ? *(const float4*)(xb + ((y << 7) + x) * CC + c4 * 4)
                            : make_float4(0.f, 0.f, 0.f, 0.f);
        }
        #pragma unroll
        for (int j = 0; j < 4; j++) {
            int cc = c4 * 4 + j;
            #pragma unroll
            for (int kk = 0; kk < 9; kk++) {
                int dy = kk / 3, dx = kk % 3;
                float4 t0 = tap[dy][dx], t1 = tap[dy][dx + 1];
                float v0 = (j == 0) ? t0.x : (j == 1) ? t0.y : (j == 2) ? t0.z : t0.w;
                float v1 = (j == 0) ? t1.x : (j == 1) ? t1.y : (j == 2) ? t1.z : t1.w;
                u64 vv0 = pack2(v0), vv1 = pack2(v1);
                const ulonglong2* wr = (const ulonglong2*)&ws[(cc * 9 + kk) * 28];
                #pragma unroll
                for (int q = 0; q < 7; q++) {
                    ulonglong2 wq = wr[q];
                    ffma2(acc[2 * q],          vv0, wq.x);
                    ffma2(acc[2 * q + 1],      vv0, wq.y);
                    ffma2(acc[14 + 2 * q],     vv1, wq.x);
                    ffma2(acc[14 + 2 * q + 1], vv1, wq.y);
                }
            }
        }
    }

    float a0[28], a1[28];
    #pragma unroll
    for (int j = 0; j < 14; j++) {
        float2 f = unpack2(acc[j]);       a0[2 * j] = f.x; a0[2 * j + 1] = f.y;
        float2 g = unpack2(acc[14 + j]);  a1[2 * j] = g.x; a1[2 * j + 1] = g.y;
    }
    int pix = (b << 14) + (h << 7) + w0;
    #pragma unroll
    for (int k = 0; k < 9; k++) {
        float by = (float)(h - 1) + (float)(k / 3);
        float bx0 = (float)(w0 - 1) + (float)(k % 3);
        float m0 = 1.0f / (1.0f + expf(-a0[18 + k]));
        float m1 = 1.0f / (1.0f + expf(-a1[18 + k]));
        g_smp[(size_t)k * NPIX + pix]     = make_float4(by + a0[2 * k], bx0 + a0[2 * k + 1], m0, 0.0f);
        g_smp[(size_t)k * NPIX + pix + 1] = make_float4(by + a1[2 * k], bx0 + 1.0f + a1[2 * k + 1], m1, 0.0f);
    }
}

// ---------------- K2: gather + main conv as block-tiled GEMM ----------------
// Block: 128 pixels x 64 outputs, 256 threads.
// Per tap: producer fills A[64c][128pix] in smem (bilinear gather), B tile 16KB;
// consumer: each thread owns 8 pixels x 4 outputs in registers (16 u64 acc).
__global__ __launch_bounds__(256) void k_main() {
    __shared__ __align__(16) float Ash[CC][128];   // 32 KB  [c][pix]
    __shared__ __align__(16) float Bsh[CC * OO];   // 16 KB  [c][o]
    int t = threadIdx.x;
    int pix0 = blockIdx.x * 128;
    int b = pix0 >> 14;
    const float* xb = g_xh + (size_t)(b << 14) * CC;

    int plocal = t & 127;          // producer: my pixel
    int chalf  = t >> 7;           // producer: c4 range 8*chalf..+7
    int pix    = pix0 + plocal;

    int pg = t & 15;               // consumer: pixels pg*8 .. pg*8+7
    int og = t >> 4;               // consumer: outputs og*4 .. og*4+3

    u64 acc[16];
    #pragma unroll
    for (int i = 0; i < 16; i++) acc[i] = 0ull;

    #pragma unroll 1
    for (int k = 0; k < 9; k++) {
        __syncthreads();
        // --- B tile (coalesced float4) ---
        const float4* bw = (const float4*)(g_wt + k * (CC * OO));
        #pragma unroll
        for (int i = 0; i < 4; i++)
            ((float4*)Bsh)[t + i * 256] = bw[t + i * 256];

        // --- A tile: bilinear gather for my pixel, 8 c4 groups ---
        float4 s = g_smp[(size_t)k * NPIX + pix];
        float y0f = floorf(s.x), x0f = floorf(s.y);
        float fy = s.x - y0f, fx = s.y - x0f;
        int y0 = (int)y0f, x0 = (int)x0f;
        float m = s.z;
        float gy = 1.0f - fy, gx = 1.0f - fx;
        bool vy0 = ((unsigned)y0 < 128u), vy1 = ((unsigned)(y0 + 1) < 128u);
        bool vx0 = ((unsigned)x0 < 128u), vx1 = ((unsigned)(x0 + 1) < 128u);
        float w00 = (vy0 && vx0) ? gy * gx * m : 0.0f;
        float w01 = (vy0 && vx1) ? gy * fx * m : 0.0f;
        float w10 = (vy1 && vx0) ? fy * gx * m : 0.0f;
        float w11 = (vy1 && vx1) ? fy * fx * m : 0.0f;
        int r0 = (vy0 ? y0 : 0) << 7;
        int r1 = (vy1 ? (y0 + 1) : 0) << 7;
        int cA  = vx0 ? x0 : 0;
        int cBx = vx1 ? (x0 + 1) : 0;
        int o00 = (r0 + cA) * CC, o01 = (r0 + cBx) * CC;
        int o10 = (r1 + cA) * CC, o11 = (r1 + cBx) * CC;

        #pragma unroll
        for (int j = 0; j < 8; j++) {
            int cb = (chalf * 8 + j) * 4;
            float4 a00 = *(const float4*)(xb + o00 + cb);
            float4 a01 = *(const float4*)(xb + o01 + cb);
            float4 a10 = *(const float4*)(xb + o10 + cb);
            float4 a11 = *(const float4*)(xb + o11 + cb);
            Ash[cb + 0][plocal] = fmaf(w00, a00.x, fmaf(w01, a01.x, fmaf(w10, a10.x, w11 * a11.x)));
            Ash[cb + 1][plocal] = fmaf(w00, a00.y, fmaf(w01, a01.y, fmaf(w10, a10.y, w11 * a11.y)));
            Ash[cb + 2][plocal] = fmaf(w00, a00.z, fmaf(w01, a01.z, fmaf(w10, a10.z, w11 * a11.z)));
            Ash[cb + 3][plocal] = fmaf(w00, a00.w, fmaf(w01, a01.w, fmaf(w10, a10.w, w11 * a11.w)));
        }
        __syncthreads();

        // --- GEMM: 64 k-steps, 8 pix x 4 out per thread ---
        #pragma unroll 8
        for (int kk = 0; kk < CC; kk++) {
            float4 a0 = *(const float4*)&Ash[kk][pg * 8];
            float4 a1 = *(const float4*)&Ash[kk][pg * 8 + 4];
            ulonglong2 bv = *(const ulonglong2*)&Bsh[kk * OO + og * 4];
            u64 p;
            p = pack2(a0.x); ffma2(acc[0],  p, bv.x); ffma2(acc[1],  p, bv.y);
            p = pack2(a0.y); ffma2(acc[2],  p, bv.x); ffma2(acc[3],  p, bv.y);
            p = pack2(a0.z); ffma2(acc[4],  p, bv.x); ffma2(acc[5],  p, bv.y);
            p = pack2(a0.w); ffma2(acc[6],  p, bv.x); ffma2(acc[7],  p, bv.y);
            p = pack2(a1.x); ffma2(acc[8],  p, bv.x); ffma2(acc[9],  p, bv.y);
            p = pack2(a1.y); ffma2(acc[10], p, bv.x); ffma2(acc[11], p, bv.y);
            p = pack2(a1.z); ffma2(acc[12], p, bv.x); ffma2(acc[13], p, bv.y);
            p = pack2(a1.w); ffma2(acc[14], p, bv.x); ffma2(acc[15], p, bv.y);
        }
    }

    #pragma unroll
    for (int i = 0; i < 8; i++) {
        float2 lo = unpack2(acc[2 * i]);
        float2 hi = unpack2(acc[2 * i + 1]);
        *(float4*)(g_raw + (size_t)(pix0 + pg * 8 + i) * OO + og * 4)
            = make_float4(lo.x, lo.y, hi.x, hi.y);
    }
}

// ---------------- K3a: per-block BN partial stats (deterministic) ----------------
__global__ void k_stats1() {
    __shared__ float ss[256], sq[256];
    int t = threadIdx.x;
    size_t base = (size_t)blockIdx.x * 256 * OO;   // 256 pixels * 64 ch
    float s = 0.0f, q = 0.0f;
    #pragma unroll 4
    for (int i = 0; i < 64; i++) {
        float v = g_raw[base + (size_t)i * 256 + t];
        s += v; q += v * v;
    }
    ss[t] = s; sq[t] = q;
    __syncthreads();
    if (t < 64) {
        float S = ss[t] + ss[t + 64] + ss[t + 128] + ss[t + 192];
        float Q = sq[t] + sq[t + 64] + sq[t + 128] + sq[t + 192];
        g_psum[blockIdx.x * 64 + t] = S;
        g_psq[blockIdx.x * 64 + t]  = Q;
    }
}

// ---------------- K3b: finalize stats -> scale/shift ----------------
__global__ void k_stats2(const float* __restrict__ gamma, const float* __restrict__ beta) {
    __shared__ float ss[256], sq[256];
    int ch = blockIdx.x, t = threadIdx.x;
    ss[t] = g_psum[t * 64 + ch];
    sq[t] = g_psq[t * 64 + ch];
    __syncthreads();
    for (int s = 128; s > 0; s >>= 1) {
        if (t < s) { ss[t] += ss[t + s]; sq[t] += sq[t + s]; }
        __syncthreads();
    }
    if (t == 0) {
        const float inv_n = 1.0f / (float)NPIX;
        float mean = ss[0] * inv_n;
        float var  = sq[0] * inv_n - mean * mean;
        float inv  = rsqrtf(var + 1e-5f);
        float sc   = gamma[ch] * inv;
        g_scale[ch] = sc;
        g_shift[ch] = beta[ch] - mean * sc;
        // conv bias cancels exactly inside batch-norm (per-channel constant)
    }
}

// ---------------- K4: BN + ReLU + NHWC->NCHW ----------------
__global__ void k_bnout(float* __restrict__ out) {
    __shared__ float s[64][65];
    __shared__ float scs[64], shs[64];
    int t = threadIdx.x;
    if (t < 64) { scs[t] = g_scale[t]; shs[t] = g_shift[t]; }
    __syncthreads();
    int pix0 = blockIdx.x * 64;
    int b = pix0 >> 14;
    int pl = pix0 & 16383;
    #pragma unroll
    for (int j = 0; j < 4; j++) {
        int idx = t + j * 256;
        int p = idx >> 4;      // 0..63 local pixel
        int q = idx & 15;      // float4 group of channels
        float4 v = *(const float4*)(g_raw + (size_t)(pix0 + p) * OO + q * 4);
        int c = q * 4;
        s[c + 0][p] = fmaxf(fmaf(v.x, scs[c + 0], shs[c + 0]), 0.0f);
        s[c + 1][p] = fmaxf(fmaf(v.y, scs[c + 1], shs[c + 1]), 0.0f);
        s[c + 2][p] = fmaxf(fmaf(v.z, scs[c + 2], shs[c + 2]), 0.0f);
        s[c + 3][p] = fmaxf(fmaf(v.w, scs[c + 3], shs[c + 3]), 0.0f);
    }
    __syncthreads();
    #pragma unroll
    for (int j = 0; j < 4; j++) {
        int idx = t + j * 256;
        int o = idx >> 4;
        int q = idx & 15;
        float4 r = make_float4(s[o][q * 4], s[o][q * 4 + 1], s[o][q * 4 + 2], s[o][q * 4 + 3]);
        *(float4*)(out + (size_t)(b * OO + o) * HWP + pl + q * 4) = r;
    }
}

// ---------------- launch ----------------
extern "C" void kernel_launch(void* const* d_in, const int* in_sizes, int n_in,
                              void* d_out, int out_size) {
    const float* x     = (const float*)d_in[0];
    const float* ow    = (const float*)d_in[1];
    const float* ob    = (const float*)d_in[2];
    const float* wt    = (const float*)d_in[3];
    // d_in[4] = bias: cancels exactly in batch norm, unused
    const float* gamma = (const float*)d_in[5];
    const float* beta  = (const float*)d_in[6];
    float* out = (float*)d_out;

    cudaFuncSetAttribute(k_offset, cudaFuncAttributeMaxDynamicSharedMemorySize, 576 * 28 * 4);

    k_transpose<<<dim3(HWP / 32, CC / 32, BB), dim3(32, 8)>>>(x);
    k_prep<<<(9 * CC * OO + 255) / 256, 256>>>(wt, ow);
    k_offset<<<BB * HH / 2, 128, 576 * 28 * 4>>>(ob);
    k_main<<<NPIX / 128, 256>>>();
    k_stats1<<<256, 256>>>();
    k_stats2<<<64, 256>>>(gamma, beta);
    k_bnout<<<NPIX / 64, 256>>>(out);
}

// round 4
// speedup vs baseline: 2.2803x; 1.6903x over previous
#include <cuda_runtime.h>
#include <cuda_bf16.h>

// Problem constants (fixed shapes): B=4, C=64, H=W=128, O=64, K=3
#define BB 4
#define CC 64
#define HH 128
#define WW 128
#define OO 64
#define HWP (HH*WW)          // 16384
#define NPIX (BB*HWP)        // 65536

typedef unsigned long long u64;

// ---------------- scratch (static device globals; no allocation) ----------------
__device__ float  g_xh[(size_t)NPIX * CC];       // x in NHWC: [b][h][w][c]   16 MB
__device__ float4 g_smp[(size_t)9 * NPIX];       // per (tap, pixel): ys, xs, mask  9.4 MB
__device__ float  g_raw[(size_t)NPIX * OO];      // pre-BN conv output, [pix][o]    16 MB
__device__ float  g_wt[9 * CC * OO];             // main weights, [k][c][o]
__device__ float  g_owt[576 * 28];               // offset weights, [c*9+kk][oc(pad to 28)]
__device__ float  g_psum[256 * OO];              // BN partial sums
__device__ float  g_psq[256 * OO];               // BN partial sumsq
__device__ float  g_scale[OO];
__device__ float  g_shift[OO];

// ---------------- packed f32x2 helpers (Blackwell FFMA2) ----------------
__device__ __forceinline__ void ffma2(u64& c, u64 a, u64 b) {
    asm("fma.rn.f32x2 %0, %1, %2, %0;" : "+l"(c) : "l"(a), "l"(b));
}
__device__ __forceinline__ u64 pack2(float v) {
    u64 r; asm("mov.b64 %0, {%1, %1};" : "=l"(r) : "f"(v)); return r;
}
__device__ __forceinline__ u64 pack2f(float a, float b) {
    u64 r; asm("mov.b64 %0, {%1, %2};" : "=l"(r) : "f"(a), "f"(b)); return r;
}
__device__ __forceinline__ float2 unpack2(u64 v) {
    float2 f; asm("mov.b64 {%0, %1}, %2;" : "=f"(f.x), "=f"(f.y) : "l"(v)); return f;
}

// ---------------- K0: NCHW -> NHWC transpose ----------------
__global__ void k_transpose(const float* __restrict__ x) {
    __shared__ float t[32][33];
    int b  = blockIdx.z;
    int c0 = blockIdx.y * 32;
    int p0 = blockIdx.x * 32;
    int tx = threadIdx.x, ty = threadIdx.y;
    #pragma unroll
    for (int j = 0; j < 4; j++) {
        int c = c0 + ty + j * 8;
        t[ty + j * 8][tx] = x[((size_t)(b * CC + c)) * HWP + p0 + tx];
    }
    __syncthreads();
    #pragma unroll
    for (int j = 0; j < 4; j++) {
        int p = p0 + ty + j * 8;
        g_xh[((size_t)(b * HWP + p)) * CC + c0 + tx] = t[tx][ty + j * 8];
    }
}

// ---------------- Kprep: weight relayouts ----------------
__global__ void k_prep(const float* __restrict__ wmain, const float* __restrict__ ow) {
    int i = blockIdx.x * 256 + threadIdx.x;
    if (i < 9 * CC * OO) {
        int k = i / (CC * OO);
        int r = i % (CC * OO);
        int c = r >> 6, o = r & 63;
        g_wt[i] = wmain[o * 576 + c * 9 + k];   // weight[o][c][ky][kx]
    }
    if (i < 576 * 28) {
        int t = i / 28, oc = i % 28;            // t = c*9 + kk
        g_owt[i] = (oc < 27) ? ow[oc * 576 + t] : 0.0f;
    }
}

// ---------------- K1: offset conv -> sample coords + mask ----------------
// block = 128 threads = 2 rows, each thread handles 2 ADJACENT pixels (w0, w0+1)
__global__ __launch_bounds__(128) void k_offset(const float* __restrict__ ob) {
    extern __shared__ float ws[];   // [576][28]
    int blk = blockIdx.x;           // 0..255
    int t = threadIdx.x;
    int b = blk >> 6;
    int h = ((blk & 63) << 1) + (t >> 6);
    int w0 = (t & 63) << 1;         // this thread: pixels (h,w0) and (h,w0+1)

    for (int i = t; i < 576 * 28; i += 128) ws[i] = g_owt[i];
    __syncthreads();

    u64 acc[28];                    // [0..13]=pixel0, [14..27]=pixel1
    #pragma unroll
    for (int j = 0; j < 14; j++) {
        float lo = (2 * j < 27) ? ob[2 * j] : 0.0f;
        float hi = (2 * j + 1 < 27) ? ob[2 * j + 1] : 0.0f;
        u64 v = pack2f(lo, hi);
        acc[j] = v; acc[14 + j] = v;
    }

    const float* xb = g_xh + (size_t)(b << 14) * CC;

    #pragma unroll 1
    for (int c4 = 0; c4 < 16; c4++) {
        float4 tap[3][4];
        #pragma unroll
        for (int dy = 0; dy < 3; dy++)
        #pragma unroll
        for (int dx = 0; dx < 4; dx++) {
            int y = h + dy - 1, x = w0 + dx - 1;
            bool v = ((unsigned)y < 128u) && ((unsigned)x < 128u);
            tap[dy][dx] = v ? *(const float4*)(xb + ((y << 7) + x) * CC + c4 * 4)
                            : make_float4(0.f, 0.f, 0.f, 0.f);
        }
        #pragma unroll
        for (int j = 0; j < 4; j++) {
            int cc = c4 * 4 + j;
            #pragma unroll
            for (int kk = 0; kk < 9; kk++) {
                int dy = kk / 3, dx = kk % 3;
                float4 t0 = tap[dy][dx], t1 = tap[dy][dx + 1];
                float v0 = (j == 0) ? t0.x : (j == 1) ? t0.y : (j == 2) ? t0.z : t0.w;
                float v1 = (j == 0) ? t1.x : (j == 1) ? t1.y : (j == 2) ? t1.z : t1.w;
                u64 vv0 = pack2(v0), vv1 = pack2(v1);
                const ulonglong2* wr = (const ulonglong2*)&ws[(cc * 9 + kk) * 28];
                #pragma unroll
                for (int q = 0; q < 7; q++) {
                    ulonglong2 wq = wr[q];
                    ffma2(acc[2 * q],          vv0, wq.x);
                    ffma2(acc[2 * q + 1],      vv0, wq.y);
                    ffma2(acc[14 + 2 * q],     vv1, wq.x);
                    ffma2(acc[14 + 2 * q + 1], vv1, wq.y);
                }
            }
        }
    }

    float a0[28], a1[28];
    #pragma unroll
    for (int j = 0; j < 14; j++) {
        float2 f = unpack2(acc[j]);       a0[2 * j] = f.x; a0[2 * j + 1] = f.y;
        float2 g = unpack2(acc[14 + j]);  a1[2 * j] = g.x; a1[2 * j + 1] = g.y;
    }
    int pix = (b << 14) + (h << 7) + w0;
    #pragma unroll
    for (int k = 0; k < 9; k++) {
        float by = (float)(h - 1) + (float)(k / 3);
        float bx0 = (float)(w0 - 1) + (float)(k % 3);
        float m0 = 1.0f / (1.0f + expf(-a0[18 + k]));
        float m1 = 1.0f / (1.0f + expf(-a1[18 + k]));
        g_smp[(size_t)k * NPIX + pix]     = make_float4(by + a0[2 * k], bx0 + a0[2 * k + 1], m0, 0.0f);
        g_smp[(size_t)k * NPIX + pix + 1] = make_float4(by + a1[2 * k], bx0 + 1.0f + a1[2 * k + 1], m1, 0.0f);
    }
}

// ---------------- K2: gather + main conv, block = 256 pix x 64 out ----------------
// Producer: 8-lane groups gather one pixel-tap cooperatively (coalesced 128B LDGs),
// store A as [pix][chan] rows (stride 68, conflict-free).
// Consumer: 8 pix x 8 out register tile per thread; A loads conflict-free,
// B loads pure broadcast. FMA-bound.
#define ASTRIDE 68
__global__ __launch_bounds__(256, 2) void k_main() {
    extern __shared__ __align__(16) float sm[];
    float* Ash = sm;                     // [256][ASTRIDE]  69632 B
    float* Bsh = sm + 256 * ASTRIDE;     // [64][64]        16384 B

    int t = threadIdx.x;
    int pix0 = blockIdx.x * 256;
    int b = pix0 >> 14;
    const float* xb = g_xh + (size_t)(b << 14) * CC;

    int gg = t >> 3;                 // producer group 0..31
    int j  = t & 7;                  // lane in group
    int pg = t & 31;                 // consumer pixel group
    int og = t >> 5;                 // consumer output group 0..7 (warp id)

    u64 acc[32];                     // [i][n]: pixel pg+32i, outputs og*8+2n..
    #pragma unroll
    for (int i = 0; i < 32; i++) acc[i] = 0ull;

    #pragma unroll 1
    for (int k = 0; k < 9; k++) {
        __syncthreads();
        // --- B tile (coalesced float4) ---
        const float4* bw = (const float4*)(g_wt + k * (CC * OO));
        #pragma unroll
        for (int i = 0; i < 4; i++)
            ((float4*)Bsh)[t + i * 256] = bw[t + i * 256];

        // --- A tile: cooperative bilinear gather ---
        #pragma unroll 1
        for (int i = 0; i < 8; i++) {
            int p = gg * 8 + i;
            float4 s = g_smp[(size_t)k * NPIX + pix0 + p];
            float y0f = floorf(s.x), x0f = floorf(s.y);
            float fy = s.x - y0f, fx = s.y - x0f;
            int y0 = (int)y0f, x0 = (int)x0f;
            float m = s.z;
            float gy = 1.0f - fy, gx = 1.0f - fx;
            bool vy0 = ((unsigned)y0 < 128u), vy1 = ((unsigned)(y0 + 1) < 128u);
            bool vx0 = ((unsigned)x0 < 128u), vx1 = ((unsigned)(x0 + 1) < 128u);
            float w00 = (vy0 && vx0) ? gy * gx * m : 0.0f;
            float w01 = (vy0 && vx1) ? gy * fx * m : 0.0f;
            float w10 = (vy1 && vx0) ? fy * gx * m : 0.0f;
            float w11 = (vy1 && vx1) ? fy * fx * m : 0.0f;
            int r0 = (vy0 ? y0 : 0) << 7;
            int r1 = (vy1 ? (y0 + 1) : 0) << 7;
            int cA  = vx0 ? x0 : 0;
            int cBx = vx1 ? (x0 + 1) : 0;
            const float* p00 = xb + (r0 + cA) * CC + 4 * j;
            const float* p01 = xb + (r0 + cBx) * CC + 4 * j;
            const float* p10 = xb + (r1 + cA) * CC + 4 * j;
            const float* p11 = xb + (r1 + cBx) * CC + 4 * j;

            float4 a00 = *(const float4*)p00;
            float4 a01 = *(const float4*)p01;
            float4 a10 = *(const float4*)p10;
            float4 a11 = *(const float4*)p11;
            float4 b00 = *(const float4*)(p00 + 32);
            float4 b01 = *(const float4*)(p01 + 32);
            float4 b10 = *(const float4*)(p10 + 32);
            float4 b11 = *(const float4*)(p11 + 32);

            float4 V0, V1;
            V0.x = fmaf(w00, a00.x, fmaf(w01, a01.x, fmaf(w10, a10.x, w11 * a11.x)));
            V0.y = fmaf(w00, a00.y, fmaf(w01, a01.y, fmaf(w10, a10.y, w11 * a11.y)));
            V0.z = fmaf(w00, a00.z, fmaf(w01, a01.z, fmaf(w10, a10.z, w11 * a11.z)));
            V0.w = fmaf(w00, a00.w, fmaf(w01, a01.w, fmaf(w10, a10.w, w11 * a11.w)));
            V1.x = fmaf(w00, b00.x, fmaf(w01, b01.x, fmaf(w10, b10.x, w11 * b11.x)));
            V1.y = fmaf(w00, b00.y, fmaf(w01, b01.y, fmaf(w10, b10.y, w11 * b11.y)));
            V1.z = fmaf(w00, b00.z, fmaf(w01, b01.z, fmaf(w10, b10.z, w11 * b11.z)));
            V1.w = fmaf(w00, b00.w, fmaf(w01, b01.w, fmaf(w10, b10.w, w11 * b11.w)));

            *(float4*)&Ash[p * ASTRIDE + 4 * j]      = V0;
            *(float4*)&Ash[p * ASTRIDE + 32 + 4 * j] = V1;
        }
        __syncthreads();

        // --- GEMM: 16 c4 steps, 8 pix x 8 out per thread ---
        #pragma unroll 4
        for (int c4 = 0; c4 < 16; c4++) {
            float4 a[8];
            #pragma unroll
            for (int i = 0; i < 8; i++)
                a[i] = *(const float4*)&Ash[(pg + 32 * i) * ASTRIDE + c4 * 4];
            #pragma unroll
            for (int cc = 0; cc < 4; cc++) {
                const float* brow = Bsh + (c4 * 4 + cc) * OO + og * 8;
                ulonglong2 b0 = *(const ulonglong2*)brow;
                ulonglong2 b1 = *(const ulonglong2*)(brow + 4);
                #pragma unroll
                for (int i = 0; i < 8; i++) {
                    float v = (cc == 0) ? a[i].x : (cc == 1) ? a[i].y
                            : (cc == 2) ? a[i].z : a[i].w;
                    u64 av = pack2(v);
                    ffma2(acc[i * 4 + 0], av, b0.x);
                    ffma2(acc[i * 4 + 1], av, b0.y);
                    ffma2(acc[i * 4 + 2], av, b1.x);
                    ffma2(acc[i * 4 + 3], av, b1.y);
                }
            }
        }
    }

    #pragma unroll
    for (int i = 0; i < 8; i++) {
        float* op = g_raw + (size_t)(pix0 + pg + 32 * i) * OO + og * 8;
        float2 l0 = unpack2(acc[i * 4 + 0]);
        float2 l1 = unpack2(acc[i * 4 + 1]);
        float2 l2 = unpack2(acc[i * 4 + 2]);
        float2 l3 = unpack2(acc[i * 4 + 3]);
        *(float4*)op       = make_float4(l0.x, l0.y, l1.x, l1.y);
        *(float4*)(op + 4) = make_float4(l2.x, l2.y, l3.x, l3.y);
    }
}

// ---------------- K3a: per-block BN partial stats (deterministic) ----------------
__global__ void k_stats1() {
    __shared__ float ss[256], sq[256];
    int t = threadIdx.x;
    size_t base = (size_t)blockIdx.x * 256 * OO;   // 256 pixels * 64 ch
    float s = 0.0f, q = 0.0f;
    #pragma unroll 4
    for (int i = 0; i < 64; i++) {
        float v = g_raw[base + (size_t)i * 256 + t];
        s += v; q += v * v;
    }
    ss[t] = s; sq[t] = q;
    __syncthreads();
    if (t < 64) {
        float S = ss[t] + ss[t + 64] + ss[t + 128] + ss[t + 192];
        float Q = sq[t] + sq[t + 64] + sq[t + 128] + sq[t + 192];
        g_psum[blockIdx.x * 64 + t] = S;
        g_psq[blockIdx.x * 64 + t]  = Q;
    }
}

// ---------------- K3b: finalize stats -> scale/shift ----------------
__global__ void k_stats2(const float* __restrict__ gamma, const float* __restrict__ beta) {
    __shared__ float ss[256], sq[256];
    int ch = blockIdx.x, t = threadIdx.x;
    ss[t] = g_psum[t * 64 + ch];
    sq[t] = g_psq[t * 64 + ch];
    __syncthreads();
    for (int s = 128; s > 0; s >>= 1) {
        if (t < s) { ss[t] += ss[t + s]; sq[t] += sq[t + s]; }
        __syncthreads();
    }
    if (t == 0) {
        const float inv_n = 1.0f / (float)NPIX;
        float mean = ss[0] * inv_n;
        float var  = sq[0] * inv_n - mean * mean;
        float inv  = rsqrtf(var + 1e-5f);
        float sc   = gamma[ch] * inv;
        g_scale[ch] = sc;
        g_shift[ch] = beta[ch] - mean * sc;
        // conv bias cancels exactly inside batch-norm (per-channel constant)
    }
}

// ---------------- K4: BN + ReLU + NHWC->NCHW ----------------
__global__ void k_bnout(float* __restrict__ out) {
    __shared__ float s[64][65];
    __shared__ float scs[64], shs[64];
    int t = threadIdx.x;
    if (t < 64) { scs[t] = g_scale[t]; shs[t] = g_shift[t]; }
    __syncthreads();
    int pix0 = blockIdx.x * 64;
    int b = pix0 >> 14;
    int pl = pix0 & 16383;
    #pragma unroll
    for (int j = 0; j < 4; j++) {
        int idx = t + j * 256;
        int p = idx >> 4;      // 0..63 local pixel
        int q = idx & 15;      // float4 group of channels
        float4 v = *(const float4*)(g_raw + (size_t)(pix0 + p) * OO + q * 4);
        int c = q * 4;
        s[c + 0][p] = fmaxf(fmaf(v.x, scs[c + 0], shs[c + 0]), 0.0f);
        s[c + 1][p] = fmaxf(fmaf(v.y, scs[c + 1], shs[c + 1]), 0.0f);
        s[c + 2][p] = fmaxf(fmaf(v.z, scs[c + 2], shs[c + 2]), 0.0f);
        s[c + 3][p] = fmaxf(fmaf(v.w, scs[c + 3], shs[c + 3]), 0.0f);
    }
    __syncthreads();
    #pragma unroll
    for (int j = 0; j < 4; j++) {
        int idx = t + j * 256;
        int o = idx >> 4;
        int q = idx & 15;
        float4 r = make_float4(s[o][q * 4], s[o][q * 4 + 1], s[o][q * 4 + 2], s[o][q * 4 + 3]);
        *(float4*)(out + (size_t)(b * OO + o) * HWP + pl + q * 4) = r;
    }
}

// ---------------- launch ----------------
extern "C" void kernel_launch(void* const* d_in, const int* in_sizes, int n_in,
                              void* d_out, int out_size) {
    const float* x     = (const float*)d_in[0];
    const float* ow    = (const float*)d_in[1];
    const float* ob    = (const float*)d_in[2];
    const float* wt    = (const float*)d_in[3];
    // d_in[4] = bias: cancels exactly in batch norm, unused
    const float* gamma = (const float*)d_in[5];
    const float* beta  = (const float*)d_in[6];
    float* out = (float*)d_out;

    cudaFuncSetAttribute(k_offset, cudaFuncAttributeMaxDynamicSharedMemorySize, 576 * 28 * 4);
    cudaFuncSetAttribute(k_main, cudaFuncAttributeMaxDynamicSharedMemorySize,
                         (256 * ASTRIDE + CC * OO) * 4);

    k_transpose<<<dim3(HWP / 32, CC / 32, BB), dim3(32, 8)>>>(x);
    k_prep<<<(9 * CC * OO + 255) / 256, 256>>>(wt, ow);
    k_offset<<<BB * HH / 2, 128, 576 * 28 * 4>>>(ob);
    k_main<<<NPIX / 256, 256, (256 * ASTRIDE + CC * OO) * 4>>>();
    k_stats1<<<256, 256>>>();
    k_stats2<<<64, 256>>>(gamma, beta);
    k_bnout<<<NPIX / 64, 256>>>(out);
}

// round 5
// speedup vs baseline: 2.3824x; 1.0448x over previous
#include <cuda_runtime.h>
#include <cuda_bf16.h>

// Problem constants (fixed shapes): B=4, C=64, H=W=128, O=64, K=3
#define BB 4
#define CC 64
#define HH 128
#define WW 128
#define OO 64
#define HWP (HH*WW)          // 16384
#define NPIX (BB*HWP)        // 65536
#define TILE 128             // pixels per k_main block
#define NBLK (NPIX / TILE)   // 512
#define ASTRIDE 68

typedef unsigned long long u64;

// ---------------- scratch (static device globals; no allocation) ----------------
__device__ float  g_xh[(size_t)NPIX * CC];       // x in NHWC: [b][h][w][c]   16 MB
__device__ float4 g_smp[(size_t)9 * NPIX];       // per (tap, pixel): ys, xs, mask  9.4 MB
__device__ float  g_raw[(size_t)NPIX * OO];      // pre-BN conv output, [pix][o]    16 MB
__device__ float  g_wt[9 * CC * OO];             // main weights, [k][c][o]
__device__ float  g_owt[576 * 28];               // offset weights, [c*9+kk][oc(pad to 28)]
__device__ float  g_psum[NBLK * OO];             // BN partial sums (per k_main block)
__device__ float  g_psq[NBLK * OO];              // BN partial sumsq
__device__ float  g_scale[OO];
__device__ float  g_shift[OO];

// ---------------- packed f32x2 helpers (Blackwell FFMA2) ----------------
__device__ __forceinline__ void ffma2(u64& c, u64 a, u64 b) {
    asm("fma.rn.f32x2 %0, %1, %2, %0;" : "+l"(c) : "l"(a), "l"(b));
}
__device__ __forceinline__ u64 pack2(float v) {
    u64 r; asm("mov.b64 %0, {%1, %1};" : "=l"(r) : "f"(v)); return r;
}
__device__ __forceinline__ u64 pack2f(float a, float b) {
    u64 r; asm("mov.b64 %0, {%1, %2};" : "=l"(r) : "f"(a), "f"(b)); return r;
}
__device__ __forceinline__ float2 unpack2(u64 v) {
    float2 f; asm("mov.b64 {%0, %1}, %2;" : "=f"(f.x), "=f"(f.y) : "l"(v)); return f;
}

// ---------------- K0: NCHW -> NHWC transpose ----------------
__global__ void k_transpose(const float* __restrict__ x) {
    __shared__ float t[32][33];
    int b  = blockIdx.z;
    int c0 = blockIdx.y * 32;
    int p0 = blockIdx.x * 32;
    int tx = threadIdx.x, ty = threadIdx.y;
    #pragma unroll
    for (int j = 0; j < 4; j++) {
        int c = c0 + ty + j * 8;
        t[ty + j * 8][tx] = x[((size_t)(b * CC + c)) * HWP + p0 + tx];
    }
    __syncthreads();
    #pragma unroll
    for (int j = 0; j < 4; j++) {
        int p = p0 + ty + j * 8;
        g_xh[((size_t)(b * HWP + p)) * CC + c0 + tx] = t[tx][ty + j * 8];
    }
}

// ---------------- Kprep: weight relayouts ----------------
__global__ void k_prep(const float* __restrict__ wmain, const float* __restrict__ ow) {
    int i = blockIdx.x * 256 + threadIdx.x;
    if (i < 9 * CC * OO) {
        int k = i / (CC * OO);
        int r = i % (CC * OO);
        int c = r >> 6, o = r & 63;
        g_wt[i] = wmain[o * 576 + c * 9 + k];   // weight[o][c][ky][kx]
    }
    if (i < 576 * 28) {
        int t = i / 28, oc = i % 28;            // t = c*9 + kk
        g_owt[i] = (oc < 27) ? ow[oc * 576 + t] : 0.0f;
    }
}

// ---------------- K1: offset conv -> sample coords + mask ----------------
__global__ __launch_bounds__(128) void k_offset(const float* __restrict__ ob) {
    extern __shared__ float ws[];   // [576][28]
    int blk = blockIdx.x;           // 0..255
    int t = threadIdx.x;
    int b = blk >> 6;
    int h = ((blk & 63) << 1) + (t >> 6);
    int w0 = (t & 63) << 1;         // this thread: pixels (h,w0) and (h,w0+1)

    for (int i = t; i < 576 * 28; i += 128) ws[i] = g_owt[i];
    __syncthreads();

    u64 acc[28];                    // [0..13]=pixel0, [14..27]=pixel1
    #pragma unroll
    for (int j = 0; j < 14; j++) {
        float lo = (2 * j < 27) ? ob[2 * j] : 0.0f;
        float hi = (2 * j + 1 < 27) ? ob[2 * j + 1] : 0.0f;
        u64 v = pack2f(lo, hi);
        acc[j] = v; acc[14 + j] = v;
    }

    const float* xb = g_xh + (size_t)(b << 14) * CC;

    #pragma unroll 1
    for (int c4 = 0; c4 < 16; c4++) {
        float4 tap[3][4];
        #pragma unroll
        for (int dy = 0; dy < 3; dy++)
        #pragma unroll
        for (int dx = 0; dx < 4; dx++) {
            int y = h + dy - 1, x = w0 + dx - 1;
            bool v = ((unsigned)y < 128u) && ((unsigned)x < 128u);
            tap[dy][dx] = v ? *(const float4*)(xb + ((y << 7) + x) * CC + c4 * 4)
                            : make_float4(0.f, 0.f, 0.f, 0.f);
        }
        #pragma unroll
        for (int j = 0; j < 4; j++) {
            int cc = c4 * 4 + j;
            #pragma unroll
            for (int kk = 0; kk < 9; kk++) {
                int dy = kk / 3, dx = kk % 3;
                float4 t0 = tap[dy][dx], t1 = tap[dy][dx + 1];
                float v0 = (j == 0) ? t0.x : (j == 1) ? t0.y : (j == 2) ? t0.z : t0.w;
                float v1 = (j == 0) ? t1.x : (j == 1) ? t1.y : (j == 2) ? t1.z : t1.w;
                u64 vv0 = pack2(v0), vv1 = pack2(v1);
                const ulonglong2* wr = (const ulonglong2*)&ws[(cc * 9 + kk) * 28];
                #pragma unroll
                for (int q = 0; q < 7; q++) {
                    ulonglong2 wq = wr[q];
                    ffma2(acc[2 * q],          vv0, wq.x);
                    ffma2(acc[2 * q + 1],      vv0, wq.y);
                    ffma2(acc[14 + 2 * q],     vv1, wq.x);
                    ffma2(acc[14 + 2 * q + 1], vv1, wq.y);
                }
            }
        }
    }

    float a0[28], a1[28];
    #pragma unroll
    for (int j = 0; j < 14; j++) {
        float2 f = unpack2(acc[j]);       a0[2 * j] = f.x; a0[2 * j + 1] = f.y;
        float2 g = unpack2(acc[14 + j]);  a1[2 * j] = g.x; a1[2 * j + 1] = g.y;
    }
    int pix = (b << 14) + (h << 7) + w0;
    #pragma unroll
    for (int k = 0; k < 9; k++) {
        float by = (float)(h - 1) + (float)(k / 3);
        float bx0 = (float)(w0 - 1) + (float)(k % 3);
        float m0 = 1.0f / (1.0f + expf(-a0[18 + k]));
        float m1 = 1.0f / (1.0f + expf(-a1[18 + k]));
        g_smp[(size_t)k * NPIX + pix]     = make_float4(by + a0[2 * k], bx0 + a0[2 * k + 1], m0, 0.0f);
        g_smp[(size_t)k * NPIX + pix + 1] = make_float4(by + a1[2 * k], bx0 + 1.0f + a1[2 * k + 1], m1, 0.0f);
    }
}

// ---------------- K2: gather + conv, software-pipelined double buffer ----------------
// Block: 128 pixels x 64 outputs, 256 threads, 2 CTAs/SM.
// Per tap: 4 sub-steps; each issues gather LDGs for tap k+1, runs 4 c4 GEMM
// steps on tap k, then retires prefetch via STS into the other buffer.
// One __syncthreads per tap. Epilogue: fused BN partial stats (shfl, fixed order).
__global__ __launch_bounds__(256, 2) void k_main() {
    extern __shared__ __align__(16) float sm[];
    float* AshB = sm;                          // [2][TILE*ASTRIDE]
    float* BshB = sm + 2 * TILE * ASTRIDE;     // [2][4096]

    int t = threadIdx.x;
    int pix0 = blockIdx.x * TILE;
    int b = pix0 >> 14;
    const float* xb = g_xh + (size_t)(b << 14) * CC;

    int gg = t >> 3;                 // producer group 0..31 -> pixels 4gg..4gg+3
    int j  = t & 7;                  // lane in group
    int pg = t & 31;                 // consumer: pixels pg+32i
    int og = t >> 5;                 // consumer: outputs og*8..+7 (og == warp id)

    u64 acc[16];
    #pragma unroll
    for (int i = 0; i < 16; i++) acc[i] = 0ull;

    // ---- prologue: gather tap 0 into buf0, load B0 ----
    {
        const float4* bw = (const float4*)g_wt;
        #pragma unroll
        for (int s = 0; s < 4; s++)
            ((float4*)BshB)[t + s * 256] = bw[t + s * 256];
        #pragma unroll 1
        for (int s = 0; s < 4; s++) {
            int p = gg * 4 + s;
            float4 sp = g_smp[(size_t)0 * NPIX + pix0 + p];
            float y0f = floorf(sp.x), x0f = floorf(sp.y);
            float fy = sp.x - y0f, fx = sp.y - x0f;
            int y0 = (int)y0f, x0 = (int)x0f;
            float m = sp.z, gy = 1.0f - fy, gx = 1.0f - fx;
            bool vy0 = ((unsigned)y0 < 128u), vy1 = ((unsigned)(y0 + 1) < 128u);
            bool vx0 = ((unsigned)x0 < 128u), vx1 = ((unsigned)(x0 + 1) < 128u);
            float w00 = (vy0 && vx0) ? gy * gx * m : 0.0f;
            float w01 = (vy0 && vx1) ? gy * fx * m : 0.0f;
            float w10 = (vy1 && vx0) ? fy * gx * m : 0.0f;
            float w11 = (vy1 && vx1) ? fy * fx * m : 0.0f;
            int r0 = (vy0 ? y0 : 0) << 7, r1 = (vy1 ? (y0 + 1) : 0) << 7;
            int cA = vx0 ? x0 : 0, cBx = vx1 ? (x0 + 1) : 0;
            const float* p00 = xb + (r0 + cA) * CC + 4 * j;
            const float* p01 = xb + (r0 + cBx) * CC + 4 * j;
            const float* p10 = xb + (r1 + cA) * CC + 4 * j;
            const float* p11 = xb + (r1 + cBx) * CC + 4 * j;
            float4 a00 = *(const float4*)p00, a01 = *(const float4*)p01;
            float4 a10 = *(const float4*)p10, a11 = *(const float4*)p11;
            float4 b00 = *(const float4*)(p00 + 32), b01 = *(const float4*)(p01 + 32);
            float4 b10 = *(const float4*)(p10 + 32), b11 = *(const float4*)(p11 + 32);
            float4 V0, V1;
            V0.x = fmaf(w00, a00.x, fmaf(w01, a01.x, fmaf(w10, a10.x, w11 * a11.x)));
            V0.y = fmaf(w00, a00.y, fmaf(w01, a01.y, fmaf(w10, a10.y, w11 * a11.y)));
            V0.z = fmaf(w00, a00.z, fmaf(w01, a01.z, fmaf(w10, a10.z, w11 * a11.z)));
            V0.w = fmaf(w00, a00.w, fmaf(w01, a01.w, fmaf(w10, a10.w, w11 * a11.w)));
            V1.x = fmaf(w00, b00.x, fmaf(w01, b01.x, fmaf(w10, b10.x, w11 * b11.x)));
            V1.y = fmaf(w00, b00.y, fmaf(w01, b01.y, fmaf(w10, b10.y, w11 * b11.y)));
            V1.z = fmaf(w00, b00.z, fmaf(w01, b01.z, fmaf(w10, b10.z, w11 * b11.z)));
            V1.w = fmaf(w00, b00.w, fmaf(w01, b01.w, fmaf(w10, b10.w, w11 * b11.w)));
            *(float4*)&AshB[p * ASTRIDE + 4 * j]      = V0;
            *(float4*)&AshB[p * ASTRIDE + 32 + 4 * j] = V1;
        }
    }
    __syncthreads();

    // ---- main pipelined loop over taps ----
    #pragma unroll 1
    for (int k = 0; k < 9; k++) {
        int cur = k & 1, nxt = cur ^ 1;
        const float* Acur = AshB + cur * (TILE * ASTRIDE);
        float*       Anxt = AshB + nxt * (TILE * ASTRIDE);
        const float* Bcur = BshB + cur * 4096;
        float*       Bnxt = BshB + nxt * 4096;
        bool pre = (k < 8);
        const float4* bw = (const float4*)(g_wt + (k + 1) * 4096);

        #pragma unroll
        for (int s = 0; s < 4; s++) {
            // --- issue prefetch loads for tap k+1, pixel gg*4+s ---
            float4 a00, a01, a10, a11, b00, b01, b10, b11, bv;
            float w00, w01, w10, w11;
            int p = gg * 4 + s;
            if (pre) {
                float4 sp = g_smp[(size_t)(k + 1) * NPIX + pix0 + p];
                float y0f = floorf(sp.x), x0f = floorf(sp.y);
                float fy = sp.x - y0f, fx = sp.y - x0f;
                int y0 = (int)y0f, x0 = (int)x0f;
                float m = sp.z, gy = 1.0f - fy, gx = 1.0f - fx;
                bool vy0 = ((unsigned)y0 < 128u), vy1 = ((unsigned)(y0 + 1) < 128u);
                bool vx0 = ((unsigned)x0 < 128u), vx1 = ((unsigned)(x0 + 1) < 128u);
                w00 = (vy0 && vx0) ? gy * gx * m : 0.0f;
                w01 = (vy0 && vx1) ? gy * fx * m : 0.0f;
                w10 = (vy1 && vx0) ? fy * gx * m : 0.0f;
                w11 = (vy1 && vx1) ? fy * fx * m : 0.0f;
                int r0 = (vy0 ? y0 : 0) << 7, r1 = (vy1 ? (y0 + 1) : 0) << 7;
                int cA = vx0 ? x0 : 0, cBx = vx1 ? (x0 + 1) : 0;
                const float* p00 = xb + (r0 + cA) * CC + 4 * j;
                const float* p01 = xb + (r0 + cBx) * CC + 4 * j;
                const float* p10 = xb + (r1 + cA) * CC + 4 * j;
                const float* p11 = xb + (r1 + cBx) * CC + 4 * j;
                a00 = *(const float4*)p00;  a01 = *(const float4*)p01;
                a10 = *(const float4*)p10;  a11 = *(const float4*)p11;
                b00 = *(const float4*)(p00 + 32); b01 = *(const float4*)(p01 + 32);
                b10 = *(const float4*)(p10 + 32); b11 = *(const float4*)(p11 + 32);
                bv  = bw[t + s * 256];
            }

            // --- GEMM on tap k: c4 = 4s .. 4s+3 ---
            #pragma unroll
            for (int c4 = 4 * s; c4 < 4 * s + 4; c4++) {
                float4 a[4];
                #pragma unroll
                for (int i = 0; i < 4; i++)
                    a[i] = *(const float4*)&Acur[(pg + 32 * i) * ASTRIDE + c4 * 4];
                #pragma unroll
                for (int cc = 0; cc < 4; cc++) {
                    const float* brow = Bcur + (c4 * 4 + cc) * OO + og * 8;
                    ulonglong2 bq0 = *(const ulonglong2*)brow;
                    ulonglong2 bq1 = *(const ulonglong2*)(brow + 4);
                    #pragma unroll
                    for (int i = 0; i < 4; i++) {
                        float v = (cc == 0) ? a[i].x : (cc == 1) ? a[i].y
                                : (cc == 2) ? a[i].z : a[i].w;
                        u64 av = pack2(v);
                        ffma2(acc[i * 4 + 0], av, bq0.x);
                        ffma2(acc[i * 4 + 1], av, bq0.y);
                        ffma2(acc[i * 4 + 2], av, bq1.x);
                        ffma2(acc[i * 4 + 3], av, bq1.y);
                    }
                }
            }

            // --- retire prefetch: combine + STS into next buffers ---
            if (pre) {
                float4 V0, V1;
                V0.x = fmaf(w00, a00.x, fmaf(w01, a01.x, fmaf(w10, a10.x, w11 * a11.x)));
                V0.y = fmaf(w00, a00.y, fmaf(w01, a01.y, fmaf(w10, a10.y, w11 * a11.y)));
                V0.z = fmaf(w00, a00.z, fmaf(w01, a01.z, fmaf(w10, a10.z, w11 * a11.z)));
                V0.w = fmaf(w00, a00.w, fmaf(w01, a01.w, fmaf(w10, a10.w, w11 * a11.w)));
                V1.x = fmaf(w00, b00.x, fmaf(w01, b01.x, fmaf(w10, b10.x, w11 * b11.x)));
                V1.y = fmaf(w00, b00.y, fmaf(w01, b01.y, fmaf(w10, b10.y, w11 * b11.y)));
                V1.z = fmaf(w00, b00.z, fmaf(w01, b01.z, fmaf(w10, b10.z, w11 * b11.z)));
                V1.w = fmaf(w00, b00.w, fmaf(w01, b01.w, fmaf(w10, b10.w, w11 * b11.w)));
                *(float4*)&Anxt[p * ASTRIDE + 4 * j]      = V0;
                *(float4*)&Anxt[p * ASTRIDE + 32 + 4 * j] = V1;
                ((float4*)Bnxt)[t + s * 256] = bv;
            }
        }
        __syncthreads();
    }

    // ---- epilogue: store g_raw + fused BN partial stats ----
    float s8[8], q8[8];
    #pragma unroll
    for (int n = 0; n < 8; n++) { s8[n] = 0.0f; q8[n] = 0.0f; }

    #pragma unroll
    for (int i = 0; i < 4; i++) {
        float2 l0 = unpack2(acc[i * 4 + 0]);
        float2 l1 = unpack2(acc[i * 4 + 1]);
        float2 l2 = unpack2(acc[i * 4 + 2]);
        float2 l3 = unpack2(acc[i * 4 + 3]);
        float* op = g_raw + (size_t)(pix0 + pg + 32 * i) * OO + og * 8;
        *(float4*)op       = make_float4(l0.x, l0.y, l1.x, l1.y);
        *(float4*)(op + 4) = make_float4(l2.x, l2.y, l3.x, l3.y);
        s8[0] += l0.x; q8[0] += l0.x * l0.x;  s8[1] += l0.y; q8[1] += l0.y * l0.y;
        s8[2] += l1.x; q8[2] += l1.x * l1.x;  s8[3] += l1.y; q8[3] += l1.y * l1.y;
        s8[4] += l2.x; q8[4] += l2.x * l2.x;  s8[5] += l2.y; q8[5] += l2.y * l2.y;
        s8[6] += l3.x; q8[6] += l3.x * l3.x;  s8[7] += l3.y; q8[7] += l3.y * l3.y;
    }
    #pragma unroll
    for (int off = 16; off > 0; off >>= 1) {
        #pragma unroll
        for (int n = 0; n < 8; n++) {
            s8[n] += __shfl_xor_sync(0xFFFFFFFF, s8[n], off);
            q8[n] += __shfl_xor_sync(0xFFFFFFFF, q8[n], off);
        }
    }
    if (pg == 0) {
        #pragma unroll
        for (int n = 0; n < 8; n++) {
            g_psum[blockIdx.x * OO + og * 8 + n] = s8[n];
            g_psq[blockIdx.x * OO + og * 8 + n]  = q8[n];
        }
    }
}

// ---------------- K3: finalize stats -> scale/shift ----------------
__global__ void k_stats2(const float* __restrict__ gamma, const float* __restrict__ beta) {
    __shared__ float ss[256], sq[256];
    int ch = blockIdx.x, t = threadIdx.x;
    ss[t] = g_psum[t * OO + ch] + g_psum[(t + 256) * OO + ch];
    sq[t] = g_psq[t * OO + ch]  + g_psq[(t + 256) * OO + ch];
    __syncthreads();
    for (int s = 128; s > 0; s >>= 1) {
        if (t < s) { ss[t] += ss[t + s]; sq[t] += sq[t + s]; }
        __syncthreads();
    }
    if (t == 0) {
        const float inv_n = 1.0f / (float)NPIX;
        float mean = ss[0] * inv_n;
        float var  = sq[0] * inv_n - mean * mean;
        float inv  = rsqrtf(var + 1e-5f);
        float sc   = gamma[ch] * inv;
        g_scale[ch] = sc;
        g_shift[ch] = beta[ch] - mean * sc;
        // conv bias cancels exactly inside batch-norm (per-channel constant)
    }
}

// ---------------- K4: BN + ReLU + NHWC->NCHW ----------------
__global__ void k_bnout(float* __restrict__ out) {
    __shared__ float s[64][65];
    __shared__ float scs[64], shs[64];
    int t = threadIdx.x;
    if (t < 64) { scs[t] = g_scale[t]; shs[t] = g_shift[t]; }
    __syncthreads();
    int pix0 = blockIdx.x * 64;
    int b = pix0 >> 14;
    int pl = pix0 & 16383;
    #pragma unroll
    for (int j = 0; j < 4; j++) {
        int idx = t + j * 256;
        int p = idx >> 4;      // 0..63 local pixel
        int q = idx & 15;      // float4 group of channels
        float4 v = *(const float4*)(g_raw + (size_t)(pix0 + p) * OO + q * 4);
        int c = q * 4;
        s[c + 0][p] = fmaxf(fmaf(v.x, scs[c + 0], shs[c + 0]), 0.0f);
        s[c + 1][p] = fmaxf(fmaf(v.y, scs[c + 1], shs[c + 1]), 0.0f);
        s[c + 2][p] = fmaxf(fmaf(v.z, scs[c + 2], shs[c + 2]), 0.0f);
        s[c + 3][p] = fmaxf(fmaf(v.w, scs[c + 3], shs[c + 3]), 0.0f);
    }
    __syncthreads();
    #pragma unroll
    for (int j = 0; j < 4; j++) {
        int idx = t + j * 256;
        int o = idx >> 4;
        int q = idx & 15;
        float4 r = make_float4(s[o][q * 4], s[o][q * 4 + 1], s[o][q * 4 + 2], s[o][q * 4 + 3]);
        *(float4*)(out + (size_t)(b * OO + o) * HWP + pl + q * 4) = r;
    }
}

// ---------------- launch ----------------
extern "C" void kernel_launch(void* const* d_in, const int* in_sizes, int n_in,
                              void* d_out, int out_size) {
    const float* x     = (const float*)d_in[0];
    const float* ow    = (const float*)d_in[1];
    const float* ob    = (const float*)d_in[2];
    const float* wt    = (const float*)d_in[3];
    // d_in[4] = bias: cancels exactly in batch norm, unused
    const float* gamma = (const float*)d_in[5];
    const float* beta  = (const float*)d_in[6];
    float* out = (float*)d_out;

    const int kmain_smem = (2 * TILE * ASTRIDE + 2 * CC * OO) * 4;   // 102400 B

    cudaFuncSetAttribute(k_offset, cudaFuncAttributeMaxDynamicSharedMemorySize, 576 * 28 * 4);
    cudaFuncSetAttribute(k_main, cudaFuncAttributeMaxDynamicSharedMemorySize, kmain_smem);

    k_transpose<<<dim3(HWP / 32, CC / 32, BB), dim3(32, 8)>>>(x);
    k_prep<<<(9 * CC * OO + 255) / 256, 256>>>(wt, ow);
    k_offset<<<BB * HH / 2, 128, 576 * 28 * 4>>>(ob);
    k_main<<<NBLK, 256, kmain_smem>>>();
    k_stats2<<<64, 256>>>(gamma, beta);
    k_bnout<<<NPIX / 64, 256>>>(out);
}

// round 9
// speedup vs baseline: 2.9485x; 1.2376x over previous
#include <cuda_runtime.h>
#include <cuda_bf16.h>
#include <cstdint>

// Problem constants (fixed shapes): B=4, C=64, H=W=128, O=64, K=3
#define BB 4
#define CC 64
#define HH 128
#define WW 128
#define OO 64
#define HWP (HH*WW)          // 16384
#define NPIX (BB*HWP)        // 65536
#define TILE 128             // pixels per k_main block
#define NBLK (NPIX / TILE)   // 512
#define BPITCH 144           // smem row pitch in bytes (72 bf16) -> conflict-free ldmatrix

typedef unsigned long long u64;
typedef unsigned int u32;

// ---------------- scratch (static device globals; no allocation) ----------------
__device__ float  g_xh[(size_t)NPIX * CC];       // x in NHWC: [b][h][w][c]   16 MB
__device__ float4 g_smp[(size_t)9 * NPIX];       // per (tap, pixel): ys, xs, mask
__device__ float  g_raw[(size_t)NPIX * OO];      // pre-BN conv output, [pix][o]
__device__ __align__(16) unsigned char g_wth[9 * OO * BPITCH];  // weight hi bf16 [tap][o][c] pitched
__device__ __align__(16) unsigned char g_wtl[9 * OO * BPITCH];  // weight lo bf16
__device__ float  g_owt[576 * 28];               // offset weights, [c*9+kk][oc(pad to 28)]
__device__ float  g_psum[256 * OO];              // BN partial sums
__device__ float  g_psq[256 * OO];               // BN partial sumsq
__device__ float  g_scale[OO];
__device__ float  g_shift[OO];

// ---------------- packed f32x2 helpers (Blackwell FFMA2) ----------------
__device__ __forceinline__ void ffma2(u64& c, u64 a, u64 b) {
    asm("fma.rn.f32x2 %0, %1, %2, %0;" : "+l"(c) : "l"(a), "l"(b));
}
__device__ __forceinline__ u64 pack2(float v) {
    u64 r; asm("mov.b64 %0, {%1, %1};" : "=l"(r) : "f"(v)); return r;
}
__device__ __forceinline__ u64 pack2f(float a, float b) {
    u64 r; asm("mov.b64 %0, {%1, %2};" : "=l"(r) : "f"(a), "f"(b)); return r;
}
__device__ __forceinline__ float2 unpack2(u64 v) {
    float2 f; asm("mov.b64 {%0, %1}, %2;" : "=f"(f.x), "=f"(f.y) : "l"(v)); return f;
}

// ---------------- mma/ldmatrix helpers (baseline PTX, works on sm_100) ----------------
__device__ __forceinline__ u32 smem_u32(const void* p) {
    u32 a;
    asm("{ .reg .u64 t; cvta.to.shared.u64 t, %1; cvt.u32.u64 %0, t; }" : "=r"(a) : "l"(p));
    return a;
}
__device__ __forceinline__ void ldsm4(u32* r, u32 addr) {
    asm volatile("ldmatrix.sync.aligned.m8n8.x4.shared.b16 {%0,%1,%2,%3}, [%4];"
        : "=r"(r[0]), "=r"(r[1]), "=r"(r[2]), "=r"(r[3]) : "r"(addr));
}
__device__ __forceinline__ void mma16816(float* c, const u32* a, u32 b0, u32 b1) {
    asm volatile(
        "mma.sync.aligned.m16n8k16.row.col.f32.bf16.bf16.f32 "
        "{%0,%1,%2,%3}, {%4,%5,%6,%7}, {%8,%9}, {%0,%1,%2,%3};"
        : "+f"(c[0]), "+f"(c[1]), "+f"(c[2]), "+f"(c[3])
        : "r"(a[0]), "r"(a[1]), "r"(a[2]), "r"(a[3]), "r"(b0), "r"(b1));
}

// k_main smem layout
#define SMA_H 0
#define SMA_L (TILE * BPITCH)                  // 18432
#define SMB_H (2 * TILE * BPITCH)              // 36864
#define SMB_L (SMB_H + OO * BPITCH)            // 46080
#define SM_TOT (SMB_L + OO * BPITCH)           // 55296

// ---------------- K0: NCHW -> NHWC transpose ----------------
__global__ void k_transpose(const float* __restrict__ x) {
    __shared__ float t[32][33];
    int b  = blockIdx.z;
    int c0 = blockIdx.y * 32;
    int p0 = blockIdx.x * 32;
    int tx = threadIdx.x, ty = threadIdx.y;
    #pragma unroll
    for (int j = 0; j < 4; j++) {
        int c = c0 + ty + j * 8;
        t[ty + j * 8][tx] = x[((size_t)(b * CC + c)) * HWP + p0 + tx];
    }
    __syncthreads();
    #pragma unroll
    for (int j = 0; j < 4; j++) {
        int p = p0 + ty + j * 8;
        g_xh[((size_t)(b * HWP + p)) * CC + c0 + tx] = t[tx][ty + j * 8];
    }
}

// ---------------- Kprep: weight relayouts (bf16 hi/lo split, pitched) ----------------
__global__ void k_prep(const float* __restrict__ wmain, const float* __restrict__ ow) {
    int i = blockIdx.x * 256 + threadIdx.x;
    if (i < 9 * OO * CC) {
        int k = i >> 12;           // tap
        int r = i & 4095;
        int o = r >> 6, c = r & 63;
        float w = wmain[o * 576 + c * 9 + k];
        __nv_bfloat16 hi = __float2bfloat16_rn(w);
        float lo = w - __bfloat162float(hi);
        __nv_bfloat16 lob = __float2bfloat16_rn(lo);
        size_t off = (size_t)k * OO * BPITCH + o * BPITCH + c * 2;
        *(__nv_bfloat16*)(g_wth + off) = hi;
        *(__nv_bfloat16*)(g_wtl + off) = lob;
    }
    if (i < 576 * 28) {
        int t = i / 28, oc = i % 28;            // t = c*9 + kk
        g_owt[i] = (oc < 27) ? ow[oc * 576 + t] : 0.0f;
    }
}

// ---------------- K1: offset conv -> sample coords + mask (FFMA2) ----------------
__global__ __launch_bounds__(128) void k_offset(const float* __restrict__ ob) {
    extern __shared__ float ws[];   // [576][28]
    int blk = blockIdx.x;           // 0..255
    int t = threadIdx.x;
    int b = blk >> 6;
    int h = ((blk & 63) << 1) + (t >> 6);
    int w0 = (t & 63) << 1;

    for (int i = t; i < 576 * 28; i += 128) ws[i] = g_owt[i];
    __syncthreads();

    u64 acc[28];
    #pragma unroll
    for (int j = 0; j < 14; j++) {
        float lo = (2 * j < 27) ? ob[2 * j] : 0.0f;
        float hi = (2 * j + 1 < 27) ? ob[2 * j + 1] : 0.0f;
        u64 v = pack2f(lo, hi);
        acc[j] = v; acc[14 + j] = v;
    }

    const float* xb = g_xh + (size_t)(b << 14) * CC;

    #pragma unroll 1
    for (int c4 = 0; c4 < 16; c4++) {
        float4 tap[3][4];
        #pragma unroll
        for (int dy = 0; dy < 3; dy++)
        #pragma unroll
        for (int dx = 0; dx < 4; dx++) {
            int y = h + dy - 1, x = w0 + dx - 1;
            bool v = ((unsigned)y < 128u) && ((unsigned)x < 128u);
            tap[dy][dx] = v ? *(const float4*)(xb + ((y << 7) + x) * CC + c4 * 4)
                            : make_float4(0.f, 0.f, 0.f, 0.f);
        }
        #pragma unroll
        for (int j = 0; j < 4; j++) {
            int cc = c4 * 4 + j;
            #pragma unroll
            for (int kk = 0; kk < 9; kk++) {
                int dy = kk / 3, dx = kk % 3;
                float4 t0 = tap[dy][dx], t1 = tap[dy][dx + 1];
                float v0 = (j == 0) ? t0.x : (j == 1) ? t0.y : (j == 2) ? t0.z : t0.w;
                float v1 = (j == 0) ? t1.x : (j == 1) ? t1.y : (j == 2) ? t1.z : t1.w;
                u64 vv0 = pack2(v0), vv1 = pack2(v1);
                const ulonglong2* wr = (const ulonglong2*)&ws[(cc * 9 + kk) * 28];
                #pragma unroll
                for (int q = 0; q < 7; q++) {
                    ulonglong2 wq = wr[q];
                    ffma2(acc[2 * q],          vv0, wq.x);
                    ffma2(acc[2 * q + 1],      vv0, wq.y);
                    ffma2(acc[14 + 2 * q],     vv1, wq.x);
                    ffma2(acc[14 + 2 * q + 1], vv1, wq.y);
                }
            }
        }
    }

    float a0[28], a1[28];
    #pragma unroll
    for (int j = 0; j < 14; j++) {
        float2 f = unpack2(acc[j]);       a0[2 * j] = f.x; a0[2 * j + 1] = f.y;
        float2 g = unpack2(acc[14 + j]);  a1[2 * j] = g.x; a1[2 * j + 1] = g.y;
    }
    int pix = (b << 14) + (h << 7) + w0;
    #pragma unroll
    for (int k = 0; k < 9; k++) {
        float by = (float)(h - 1) + (float)(k / 3);
        float bx0 = (float)(w0 - 1) + (float)(k % 3);
        float m0 = 1.0f / (1.0f + expf(-a0[18 + k]));
        float m1 = 1.0f / (1.0f + expf(-a1[18 + k]));
        g_smp[(size_t)k * NPIX + pix]     = make_float4(by + a0[2 * k], bx0 + a0[2 * k + 1], m0, 0.0f);
        g_smp[(size_t)k * NPIX + pix + 1] = make_float4(by + a1[2 * k], bx0 + 1.0f + a1[2 * k + 1], m1, 0.0f);
    }
}

// ---------------- K2: gather + mma.sync bf16-split GEMM ----------------
// Block: 128 pixels x 64 outputs, 256 threads (8 warps). Warp tile m32 x n32.
// Per tap: producers gather into pitched bf16 hi/lo A tiles + copy B hi/lo;
// consumers run ldmatrix + mma.sync m16n8k16 (3-term bf16 split, fp32 acc).
__global__ __launch_bounds__(256, 2) void k_main() {
    extern __shared__ __align__(16) char smc[];
    u32 sb = smem_u32(smc);

    int t = threadIdx.x;
    int w = t >> 5, lane = t & 31;
    int pix0 = blockIdx.x * TILE;
    int b = pix0 >> 14;
    const float* xb = g_xh + (size_t)(b << 14) * CC;

    int gg = t >> 3;   // gather group 0..31 -> pixels 4gg..4gg+3
    int j  = t & 7;    // lane in group -> channels 4j..4j+3 and 32+4j..32+4j+3

    int mb = (w & 3) * 32;    // warp m base (pixels)
    int nb = (w >> 2) * 32;   // warp n base (outputs)

    float acc[2][4][4];
    #pragma unroll
    for (int mi = 0; mi < 2; mi++)
        #pragma unroll
        for (int ni = 0; ni < 4; ni++)
            #pragma unroll
            for (int q = 0; q < 4; q++) acc[mi][ni][q] = 0.0f;

    // ldmatrix addresses (constant per thread across taps)
    u32 aAddr[2];
    #pragma unroll
    for (int mi = 0; mi < 2; mi++)
        aAddr[mi] = sb + SMA_H + (mb + 16 * mi + (lane & 15)) * BPITCH + (lane >> 4) * 16;
    u32 bAddr[2];
    #pragma unroll
    for (int half = 0; half < 2; half++) {
        int nrow = nb + 16 * half + ((lane >> 4) & 1) * 8 + (lane & 7);
        bAddr[half] = sb + SMB_H + nrow * BPITCH + ((lane >> 3) & 1) * 16;
    }

    #pragma unroll 1
    for (int k = 0; k < 9; k++) {
        __syncthreads();   // previous GEMM finished reading smem

        // --- B tiles: copy 9216B hi + 9216B lo (uint4, coalesced) ---
        {
            const uint4* sh = (const uint4*)(g_wth + (size_t)k * OO * BPITCH);
            const uint4* sl = (const uint4*)(g_wtl + (size_t)k * OO * BPITCH);
            uint4* dh = (uint4*)(smc + SMB_H);
            uint4* dl = (uint4*)(smc + SMB_L);
            #pragma unroll
            for (int i = 0; i < 3; i++) {
                int idx = t + i * 256;
                if (idx < 576) { dh[idx] = sh[idx]; dl[idx] = sl[idx]; }
            }
        }

        // --- A tiles: cooperative bilinear gather + bf16 hi/lo split ---
        #pragma unroll 1
        for (int s = 0; s < 4; s++) {
            int p = gg * 4 + s;
            float4 sp = g_smp[(size_t)k * NPIX + pix0 + p];
            float y0f = floorf(sp.x), x0f = floorf(sp.y);
            float fy = sp.x - y0f, fx = sp.y - x0f;
            int y0 = (int)y0f, x0 = (int)x0f;
            float m = sp.z, gy = 1.0f - fy, gx = 1.0f - fx;
            bool vy0 = ((unsigned)y0 < 128u), vy1 = ((unsigned)(y0 + 1) < 128u);
            bool vx0 = ((unsigned)x0 < 128u), vx1 = ((unsigned)(x0 + 1) < 128u);
            float w00 = (vy0 && vx0) ? gy * gx * m : 0.0f;
            float w01 = (vy0 && vx1) ? gy * fx * m : 0.0f;
            float w10 = (vy1 && vx0) ? fy * gx * m : 0.0f;
            float w11 = (vy1 && vx1) ? fy * fx * m : 0.0f;
            int r0 = (vy0 ? y0 : 0) << 7, r1 = (vy1 ? (y0 + 1) : 0) << 7;
            int cA = vx0 ? x0 : 0, cBx = vx1 ? (x0 + 1) : 0;
            const float* p00 = xb + (r0 + cA) * CC + 4 * j;
            const float* p01 = xb + (r0 + cBx) * CC + 4 * j;
            const float* p10 = xb + (r1 + cA) * CC + 4 * j;
            const float* p11 = xb + (r1 + cBx) * CC + 4 * j;
            float4 a00 = *(const float4*)p00, a01 = *(const float4*)p01;
            float4 a10 = *(const float4*)p10, a11 = *(const float4*)p11;
            float4 b00 = *(const float4*)(p00 + 32), b01 = *(const float4*)(p01 + 32);
            float4 b10 = *(const float4*)(p10 + 32), b11 = *(const float4*)(p11 + 32);

            float4 V0, V1;
            V0.x = fmaf(w00, a00.x, fmaf(w01, a01.x, fmaf(w10, a10.x, w11 * a11.x)));
            V0.y = fmaf(w00, a00.y, fmaf(w01, a01.y, fmaf(w10, a10.y, w11 * a11.y)));
            V0.z = fmaf(w00, a00.z, fmaf(w01, a01.z, fmaf(w10, a10.z, w11 * a11.z)));
            V0.w = fmaf(w00, a00.w, fmaf(w01, a01.w, fmaf(w10, a10.w, w11 * a11.w)));
            V1.x = fmaf(w00, b00.x, fmaf(w01, b01.x, fmaf(w10, b10.x, w11 * b11.x)));
            V1.y = fmaf(w00, b00.y, fmaf(w01, b01.y, fmaf(w10, b10.y, w11 * b11.y)));
            V1.z = fmaf(w00, b00.z, fmaf(w01, b01.z, fmaf(w10, b10.z, w11 * b11.z)));
            V1.w = fmaf(w00, b00.w, fmaf(w01, b01.w, fmaf(w10, b10.w, w11 * b11.w)));

            // split V0 (ch 4j..4j+3) and V1 (ch 32+4j..)
            float vf[8] = {V0.x, V0.y, V0.z, V0.w, V1.x, V1.y, V1.z, V1.w};
            u32 hp[4], lp[4];
            #pragma unroll
            for (int q = 0; q < 4; q++) {
                __nv_bfloat16 h0 = __float2bfloat16_rn(vf[2 * q]);
                __nv_bfloat16 h1 = __float2bfloat16_rn(vf[2 * q + 1]);
                float l0 = vf[2 * q]     - __bfloat162float(h0);
                float l1 = vf[2 * q + 1] - __bfloat162float(h1);
                __nv_bfloat162 hh; hh.x = h0; hh.y = h1;
                __nv_bfloat162 ll = __floats2bfloat162_rn(l0, l1);
                memcpy(&hp[q], &hh, 4);
                memcpy(&lp[q], &ll, 4);
            }
            char* rowH = smc + SMA_H + p * BPITCH;
            char* rowL = smc + SMA_L + p * BPITCH;
            *(uint2*)(rowH + 8 * j)      = make_uint2(hp[0], hp[1]);
            *(uint2*)(rowH + 64 + 8 * j) = make_uint2(hp[2], hp[3]);
            *(uint2*)(rowL + 8 * j)      = make_uint2(lp[0], lp[1]);
            *(uint2*)(rowL + 64 + 8 * j) = make_uint2(lp[2], lp[3]);
        }
        __syncthreads();

        // --- GEMM: 4 k16 steps ---
        #pragma unroll
        for (int ks = 0; ks < 4; ks++) {
            u32 ah[2][4], al[2][4];
            #pragma unroll
            for (int mi = 0; mi < 2; mi++) {
                ldsm4(ah[mi], aAddr[mi] + ks * 32);
                ldsm4(al[mi], aAddr[mi] + ks * 32 + (SMA_L - SMA_H));
            }
            #pragma unroll
            for (int half = 0; half < 2; half++) {
                u32 bh[4], bl[4];
                ldsm4(bh, bAddr[half] + ks * 32);
                ldsm4(bl, bAddr[half] + ks * 32 + (SMB_L - SMB_H));
                #pragma unroll
                for (int mi = 0; mi < 2; mi++) {
                    mma16816(acc[mi][2 * half],     ah[mi], bh[0], bh[1]);
                    mma16816(acc[mi][2 * half],     ah[mi], bl[0], bl[1]);
                    mma16816(acc[mi][2 * half],     al[mi], bh[0], bh[1]);
                    mma16816(acc[mi][2 * half + 1], ah[mi], bh[2], bh[3]);
                    mma16816(acc[mi][2 * half + 1], ah[mi], bl[2], bl[3]);
                    mma16816(acc[mi][2 * half + 1], al[mi], bh[2], bh[3]);
                }
            }
        }
    }

    // ---- epilogue: fragment -> g_raw ----
    int er = lane >> 2, ec = (lane & 3) * 2;
    #pragma unroll
    for (int mi = 0; mi < 2; mi++) {
        #pragma unroll
        for (int ni = 0; ni < 4; ni++) {
            int pix = pix0 + mb + 16 * mi + er;
            int o = nb + 8 * ni + ec;
            *(float2*)(g_raw + (size_t)pix * OO + o)       = make_float2(acc[mi][ni][0], acc[mi][ni][1]);
            *(float2*)(g_raw + (size_t)(pix + 8) * OO + o) = make_float2(acc[mi][ni][2], acc[mi][ni][3]);
        }
    }
}

// ---------------- K3a: per-block BN partial stats (deterministic) ----------------
__global__ void k_stats1() {
    __shared__ float ss[256], sq[256];
    int t = threadIdx.x;
    size_t base = (size_t)blockIdx.x * 256 * OO;   // 256 pixels * 64 ch
    float s = 0.0f, q = 0.0f;
    #pragma unroll 4
    for (int i = 0; i < 64; i++) {
        float v = g_raw[base + (size_t)i * 256 + t];
        s += v; q += v * v;
    }
    ss[t] = s; sq[t] = q;
    __syncthreads();
    if (t < 64) {
        float S = ss[t] + ss[t + 64] + ss[t + 128] + ss[t + 192];
        float Q = sq[t] + sq[t + 64] + sq[t + 128] + sq[t + 192];
        g_psum[blockIdx.x * 64 + t] = S;
        g_psq[blockIdx.x * 64 + t]  = Q;
    }
}

// ---------------- K3b: finalize stats -> scale/shift ----------------
__global__ void k_stats2(const float* __restrict__ gamma, const float* __restrict__ beta) {
    __shared__ float ss[256], sq[256];
    int ch = blockIdx.x, t = threadIdx.x;
    ss[t] = g_psum[t * 64 + ch];
    sq[t] = g_psq[t * 64 + ch];
    __syncthreads();
    for (int s = 128; s > 0; s >>= 1) {
        if (t < s) { ss[t] += ss[t + s]; sq[t] += sq[t + s]; }
        __syncthreads();
    }
    if (t == 0) {
        const float inv_n = 1.0f / (float)NPIX;
        float mean = ss[0] * inv_n;
        float var  = sq[0] * inv_n - mean * mean;
        float inv  = rsqrtf(var + 1e-5f);
        float sc   = gamma[ch] * inv;
        g_scale[ch] = sc;
        g_shift[ch] = beta[ch] - mean * sc;
        // conv bias cancels exactly inside batch-norm (per-channel constant)
    }
}

// ---------------- K4: BN + ReLU + NHWC->NCHW ----------------
__global__ void k_bnout(float* __restrict__ out) {
    __shared__ float s[64][65];
    __shared__ float scs[64], shs[64];
    int t = threadIdx.x;
    if (t < 64) { scs[t] = g_scale[t]; shs[t] = g_shift[t]; }
    __syncthreads();
    int pix0 = blockIdx.x * 64;
    int b = pix0 >> 14;
    int pl = pix0 & 16383;
    #pragma unroll
    for (int j = 0; j < 4; j++) {
        int idx = t + j * 256;
        int p = idx >> 4;      // 0..63 local pixel
        int q = idx & 15;      // float4 group of channels
        float4 v = *(const float4*)(g_raw + (size_t)(pix0 + p) * OO + q * 4);
        int c = q * 4;
        s[c + 0][p] = fmaxf(fmaf(v.x, scs[c + 0], shs[c + 0]), 0.0f);
        s[c + 1][p] = fmaxf(fmaf(v.y, scs[c + 1], shs[c + 1]), 0.0f);
        s[c + 2][p] = fmaxf(fmaf(v.z, scs[c + 2], shs[c + 2]), 0.0f);
        s[c + 3][p] = fmaxf(fmaf(v.w, scs[c + 3], shs[c + 3]), 0.0f);
    }
    __syncthreads();
    #pragma unroll
    for (int j = 0; j < 4; j++) {
        int idx = t + j * 256;
        int o = idx >> 4;
        int q = idx & 15;
        float4 r = make_float4(s[o][q * 4], s[o][q * 4 + 1], s[o][q * 4 + 2], s[o][q * 4 + 3]);
        *(float4*)(out + (size_t)(b * OO + o) * HWP + pl + q * 4) = r;
    }
}

// ---------------- launch ----------------
extern "C" void kernel_launch(void* const* d_in, const int* in_sizes, int n_in,
                              void* d_out, int out_size) {
    const float* x     = (const float*)d_in[0];
    const float* ow    = (const float*)d_in[1];
    const float* ob    = (const float*)d_in[2];
    const float* wt    = (const float*)d_in[3];
    // d_in[4] = bias: cancels exactly in batch norm, unused
    const float* gamma = (const float*)d_in[5];
    const float* beta  = (const float*)d_in[6];
    float* out = (float*)d_out;

    cudaFuncSetAttribute(k_offset, cudaFuncAttributeMaxDynamicSharedMemorySize, 576 * 28 * 4);
    cudaFuncSetAttribute(k_main, cudaFuncAttributeMaxDynamicSharedMemorySize, SM_TOT);

    k_transpose<<<dim3(HWP / 32, CC / 32, BB), dim3(32, 8)>>>(x);
    k_prep<<<(9 * OO * CC + 255) / 256, 256>>>(wt, ow);
    k_offset<<<BB * HH / 2, 128, 576 * 28 * 4>>>(ob);
    k_main<<<NBLK, 256, SM_TOT>>>();
    k_stats1<<<256, 256>>>();
    k_stats2<<<64, 256>>>(gamma, beta);
    k_bnout<<<NPIX / 64, 256>>>(out);
}

// round 12
// speedup vs baseline: 3.1092x; 1.0545x over previous
#include <cuda_runtime.h>
#include <cuda_bf16.h>
#include <cstdint>

// Problem constants (fixed shapes): B=4, C=64, H=W=128, O=64, K=3
#define BB 4
#define CC 64
#define HH 128
#define WW 128
#define OO 64
#define HWP (HH*WW)          // 16384
#define NPIX (BB*HWP)        // 65536
#define TILE 128             // pixels per k_main block
#define NBLK (NPIX / TILE)   // 512
#define BPITCH 144           // smem row pitch bytes (72 bf16): 144/16=9 -> conflict-free ldmatrix

typedef unsigned long long u64;
typedef unsigned int u32;

// ---------------- scratch (static device globals; no allocation) ----------------
__device__ float  g_xh[(size_t)NPIX * CC];       // x in NHWC: [b][h][w][c]   16 MB
__device__ float4 g_smp[(size_t)9 * NPIX];       // per (tap, pixel): ys, xs, mask
__device__ float  g_raw[(size_t)NPIX * OO];      // pre-BN conv output, [pix][o]
__device__ __align__(16) unsigned char g_wth[9 * OO * BPITCH];  // weight hi bf16 [tap][o][c] pitched
__device__ __align__(16) unsigned char g_wtl[9 * OO * BPITCH];  // weight lo bf16
__device__ float  g_owt[576 * 28];               // offset weights, [c*9+kk][oc(pad to 28)]
__device__ float  g_psum[NBLK * OO];             // BN partial sums (per k_main block)
__device__ float  g_psq[NBLK * OO];              // BN partial sumsq
__device__ float  g_scale[OO];
__device__ float  g_shift[OO];

// ---------------- packed f32x2 helpers (Blackwell FFMA2) ----------------
__device__ __forceinline__ void ffma2(u64& c, u64 a, u64 b) {
    asm("fma.rn.f32x2 %0, %1, %2, %0;" : "+l"(c) : "l"(a), "l"(b));
}
__device__ __forceinline__ u64 pack2(float v) {
    u64 r; asm("mov.b64 %0, {%1, %1};" : "=l"(r) : "f"(v)); return r;
}
__device__ __forceinline__ u64 pack2f(float a, float b) {
    u64 r; asm("mov.b64 %0, {%1, %2};" : "=l"(r) : "f"(a), "f"(b)); return r;
}
__device__ __forceinline__ float2 unpack2(u64 v) {
    float2 f; asm("mov.b64 {%0, %1}, %2;" : "=f"(f.x), "=f"(f.y) : "l"(v)); return f;
}

// ---------------- mma/ldmatrix helpers (baseline PTX, works on sm_100) ----------------
__device__ __forceinline__ u32 smem_u32(const void* p) {
    u32 a;
    asm("{ .reg .u64 t; cvta.to.shared.u64 t, %1; cvt.u32.u64 %0, t; }" : "=r"(a) : "l"(p));
    return a;
}
__device__ __forceinline__ void ldsm4(u32* r, u32 addr) {
    asm volatile("ldmatrix.sync.aligned.m8n8.x4.shared.b16 {%0,%1,%2,%3}, [%4];"
        : "=r"(r[0]), "=r"(r[1]), "=r"(r[2]), "=r"(r[3]) : "r"(addr));
}
__device__ __forceinline__ void mma16816(float* c, const u32* a, u32 b0, u32 b1) {
    asm volatile(
        "mma.sync.aligned.m16n8k16.row.col.f32.bf16.bf16.f32 "
        "{%0,%1,%2,%3}, {%4,%5,%6,%7}, {%8,%9}, {%0,%1,%2,%3};"
        : "+f"(c[0]), "+f"(c[1]), "+f"(c[2]), "+f"(c[3])
        : "r"(a[0]), "r"(a[1]), "r"(a[2]), "r"(a[3]), "r"(b0), "r"(b1));
}

// k_main smem layout: double-buffered A hi/lo + B hi/lo
#define BUFSZ   55296
#define SMA_H(b) ((b) * BUFSZ + 0)
#define SMA_L(b) ((b) * BUFSZ + TILE * BPITCH)              // +18432
#define SMB_H(b) ((b) * BUFSZ + 2 * TILE * BPITCH)          // +36864
#define SMB_L(b) ((b) * BUFSZ + 2 * TILE * BPITCH + OO * BPITCH)  // +46080
#define SM_TOT  (2 * BUFSZ)                                 // 110592

// ---------------- K0: NCHW -> NHWC transpose ----------------
__global__ void k_transpose(const float* __restrict__ x) {
    __shared__ float t[32][33];
    int b  = blockIdx.z;
    int c0 = blockIdx.y * 32;
    int p0 = blockIdx.x * 32;
    int tx = threadIdx.x, ty = threadIdx.y;
    #pragma unroll
    for (int j = 0; j < 4; j++) {
        int c = c0 + ty + j * 8;
        t[ty + j * 8][tx] = x[((size_t)(b * CC + c)) * HWP + p0 + tx];
    }
    __syncthreads();
    #pragma unroll
    for (int j = 0; j < 4; j++) {
        int p = p0 + ty + j * 8;
        g_xh[((size_t)(b * HWP + p)) * CC + c0 + tx] = t[tx][ty + j * 8];
    }
}

// ---------------- Kprep: weight relayouts (bf16 hi/lo split, pitched) ----------------
__global__ void k_prep(const float* __restrict__ wmain, const float* __restrict__ ow) {
    int i = blockIdx.x * 256 + threadIdx.x;
    if (i < 9 * OO * CC) {
        int k = i >> 12;           // tap
        int r = i & 4095;
        int o = r >> 6, c = r & 63;
        float w = wmain[o * 576 + c * 9 + k];
        __nv_bfloat16 hi = __float2bfloat16_rn(w);
        float lo = w - __bfloat162float(hi);
        __nv_bfloat16 lob = __float2bfloat16_rn(lo);
        size_t off = (size_t)k * OO * BPITCH + o * BPITCH + c * 2;
        *(__nv_bfloat16*)(g_wth + off) = hi;
        *(__nv_bfloat16*)(g_wtl + off) = lob;
    }
    if (i < 576 * 28) {
        int t = i / 28, oc = i % 28;            // t = c*9 + kk
        g_owt[i] = (oc < 27) ? ow[oc * 576 + t] : 0.0f;
    }
}

// ---------------- K1: offset conv -> sample coords + mask (FFMA2) ----------------
__global__ __launch_bounds__(128) void k_offset(const float* __restrict__ ob) {
    extern __shared__ float ws[];   // [576][28]
    int blk = blockIdx.x;           // 0..255
    int t = threadIdx.x;
    int b = blk >> 6;
    int h = ((blk & 63) << 1) + (t >> 6);
    int w0 = (t & 63) << 1;

    for (int i = t; i < 576 * 28; i += 128) ws[i] = g_owt[i];
    __syncthreads();

    u64 acc[28];
    #pragma unroll
    for (int j = 0; j < 14; j++) {
        float lo = (2 * j < 27) ? ob[2 * j] : 0.0f;
        float hi = (2 * j + 1 < 27) ? ob[2 * j + 1] : 0.0f;
        u64 v = pack2f(lo, hi);
        acc[j] = v; acc[14 + j] = v;
    }

    const float* xb = g_xh + (size_t)(b << 14) * CC;

    #pragma unroll 1
    for (int c4 = 0; c4 < 16; c4++) {
        float4 tap[3][4];
        #pragma unroll
        for (int dy = 0; dy < 3; dy++)
        #pragma unroll
        for (int dx = 0; dx < 4; dx++) {
            int y = h + dy - 1, x = w0 + dx - 1;
            bool v = ((unsigned)y < 128u) && ((unsigned)x < 128u);
            tap[dy][dx] = v ? *(const float4*)(xb + ((y << 7) + x) * CC + c4 * 4)
                            : make_float4(0.f, 0.f, 0.f, 0.f);
        }
        #pragma unroll
        for (int j = 0; j < 4; j++) {
            int cc = c4 * 4 + j;
            #pragma unroll
            for (int kk = 0; kk < 9; kk++) {
                int dy = kk / 3, dx = kk % 3;
                float4 t0 = tap[dy][dx], t1 = tap[dy][dx + 1];
                float v0 = (j == 0) ? t0.x : (j == 1) ? t0.y : (j == 2) ? t0.z : t0.w;
                float v1 = (j == 0) ? t1.x : (j == 1) ? t1.y : (j == 2) ? t1.z : t1.w;
                u64 vv0 = pack2(v0), vv1 = pack2(v1);
                const ulonglong2* wr = (const ulonglong2*)&ws[(cc * 9 + kk) * 28];
                #pragma unroll
                for (int q = 0; q < 7; q++) {
                    ulonglong2 wq = wr[q];
                    ffma2(acc[2 * q],          vv0, wq.x);
                    ffma2(acc[2 * q + 1],      vv0, wq.y);
                    ffma2(acc[14 + 2 * q],     vv1, wq.x);
                    ffma2(acc[14 + 2 * q + 1], vv1, wq.y);
                }
            }
        }
    }

    float a0[28], a1[28];
    #pragma unroll
    for (int j = 0; j < 14; j++) {
        float2 f = unpack2(acc[j]);       a0[2 * j] = f.x; a0[2 * j + 1] = f.y;
        float2 g = unpack2(acc[14 + j]);  a1[2 * j] = g.x; a1[2 * j + 1] = g.y;
    }
    int pix = (b << 14) + (h << 7) + w0;
    #pragma unroll
    for (int k = 0; k < 9; k++) {
        float by = (float)(h - 1) + (float)(k / 3);
        float bx0 = (float)(w0 - 1) + (float)(k % 3);
        float m0 = 1.0f / (1.0f + expf(-a0[18 + k]));
        float m1 = 1.0f / (1.0f + expf(-a1[18 + k]));
        g_smp[(size_t)k * NPIX + pix]     = make_float4(by + a0[2 * k], bx0 + a0[2 * k + 1], m0, 0.0f);
        g_smp[(size_t)k * NPIX + pix + 1] = make_float4(by + a1[2 * k], bx0 + 1.0f + a1[2 * k + 1], m1, 0.0f);
    }
}

// ---------------- gather helpers for k_main ----------------
struct Pref {
    float4 a00, a01, a10, a11, b00, b01, b10, b11;
    float w00, w01, w10, w11;
};
__device__ __forceinline__ Pref issueGather(const float* xb, float4 sp, int j) {
    Pref P;
    float y0f = floorf(sp.x), x0f = floorf(sp.y);
    float fy = sp.x - y0f, fx = sp.y - x0f;
    int y0 = (int)y0f, x0 = (int)x0f;
    float m = sp.z, gy = 1.0f - fy, gx = 1.0f - fx;
    bool vy0 = ((unsigned)y0 < 128u), vy1 = ((unsigned)(y0 + 1) < 128u);
    bool vx0 = ((unsigned)x0 < 128u), vx1 = ((unsigned)(x0 + 1) < 128u);
    P.w00 = (vy0 && vx0) ? gy * gx * m : 0.0f;
    P.w01 = (vy0 && vx1) ? gy * fx * m : 0.0f;
    P.w10 = (vy1 && vx0) ? fy * gx * m : 0.0f;
    P.w11 = (vy1 && vx1) ? fy * fx * m : 0.0f;
    int r0 = (vy0 ? y0 : 0) << 7, r1 = (vy1 ? (y0 + 1) : 0) << 7;
    int cA = vx0 ? x0 : 0, cBx = vx1 ? (x0 + 1) : 0;
    const float* p00 = xb + (r0 + cA) * CC + 4 * j;
    const float* p01 = xb + (r0 + cBx) * CC + 4 * j;
    const float* p10 = xb + (r1 + cA) * CC + 4 * j;
    const float* p11 = xb + (r1 + cBx) * CC + 4 * j;
    P.a00 = *(const float4*)p00;        P.a01 = *(const float4*)p01;
    P.a10 = *(const float4*)p10;        P.a11 = *(const float4*)p11;
    P.b00 = *(const float4*)(p00 + 32); P.b01 = *(const float4*)(p01 + 32);
    P.b10 = *(const float4*)(p10 + 32); P.b11 = *(const float4*)(p11 + 32);
    return P;
}
__device__ __forceinline__ void retireGather(const Pref& P, char* rowH, char* rowL, int j) {
    float4 V0, V1;
    V0.x = fmaf(P.w00, P.a00.x, fmaf(P.w01, P.a01.x, fmaf(P.w10, P.a10.x, P.w11 * P.a11.x)));
    V0.y = fmaf(P.w00, P.a00.y, fmaf(P.w01, P.a01.y, fmaf(P.w10, P.a10.y, P.w11 * P.a11.y)));
    V0.z = fmaf(P.w00, P.a00.z, fmaf(P.w01, P.a01.z, fmaf(P.w10, P.a10.z, P.w11 * P.a11.z)));
    V0.w = fmaf(P.w00, P.a00.w, fmaf(P.w01, P.a01.w, fmaf(P.w10, P.a10.w, P.w11 * P.a11.w)));
    V1.x = fmaf(P.w00, P.b00.x, fmaf(P.w01, P.b01.x, fmaf(P.w10, P.b10.x, P.w11 * P.b11.x)));
    V1.y = fmaf(P.w00, P.b00.y, fmaf(P.w01, P.b01.y, fmaf(P.w10, P.b10.y, P.w11 * P.b11.y)));
    V1.z = fmaf(P.w00, P.b00.z, fmaf(P.w01, P.b01.z, fmaf(P.w10, P.b10.z, P.w11 * P.b11.z)));
    V1.w = fmaf(P.w00, P.b00.w, fmaf(P.w01, P.b01.w, fmaf(P.w10, P.b10.w, P.w11 * P.b11.w)));
    float vf[8] = {V0.x, V0.y, V0.z, V0.w, V1.x, V1.y, V1.z, V1.w};
    u32 hp[4], lp[4];
    #pragma unroll
    for (int q = 0; q < 4; q++) {
        __nv_bfloat16 h0 = __float2bfloat16_rn(vf[2 * q]);
        __nv_bfloat16 h1 = __float2bfloat16_rn(vf[2 * q + 1]);
        float l0 = vf[2 * q]     - __bfloat162float(h0);
        float l1 = vf[2 * q + 1] - __bfloat162float(h1);
        __nv_bfloat162 hh; hh.x = h0; hh.y = h1;
        __nv_bfloat162 ll = __floats2bfloat162_rn(l0, l1);
        memcpy(&hp[q], &hh, 4);
        memcpy(&lp[q], &ll, 4);
    }
    *(uint2*)(rowH + 8 * j)      = make_uint2(hp[0], hp[1]);
    *(uint2*)(rowH + 64 + 8 * j) = make_uint2(hp[2], hp[3]);
    *(uint2*)(rowL + 8 * j)      = make_uint2(lp[0], lp[1]);
    *(uint2*)(rowL + 64 + 8 * j) = make_uint2(lp[2], lp[3]);
}

// ---------------- K2: gather + mma.sync, pipelined (1 sync/tap) + fused BN stats ----------------
__global__ __launch_bounds__(256, 2) void k_main() {
    extern __shared__ __align__(16) char smc[];
    u32 sb = smem_u32(smc);

    int t = threadIdx.x;
    int w = t >> 5, lane = t & 31;
    int pix0 = blockIdx.x * TILE;
    int b = pix0 >> 14;
    const float* xb = g_xh + (size_t)(b << 14) * CC;

    int gg = t >> 3;   // gather group 0..31 -> pixels 4gg..4gg+3
    int j  = t & 7;    // lane in group -> channels 4j..4j+3 and 32+4j..32+4j+3

    int mb = (w & 3) * 32;    // warp m base (pixels)
    int nb = (w >> 2) * 32;   // warp n base (outputs)

    float acc[2][4][4];
    #pragma unroll
    for (int mi = 0; mi < 2; mi++)
        #pragma unroll
        for (int ni = 0; ni < 4; ni++)
            #pragma unroll
            for (int q = 0; q < 4; q++) acc[mi][ni][q] = 0.0f;

    // ldmatrix offsets within a tile (constant per thread)
    u32 aOff[2];
    #pragma unroll
    for (int mi = 0; mi < 2; mi++)
        aOff[mi] = (mb + 16 * mi + (lane & 15)) * BPITCH + (lane >> 4) * 16;
    u32 bOff[2];
    #pragma unroll
    for (int half = 0; half < 2; half++) {
        int nrow = nb + 16 * half + ((lane >> 4) & 1) * 8 + (lane & 7);
        bOff[half] = nrow * BPITCH + ((lane >> 3) & 1) * 16;
    }

    // ---- prologue: B0 copy + gather tap 0 into buf0 ----
    {
        const uint4* sh = (const uint4*)g_wth;
        const uint4* sl = (const uint4*)g_wtl;
        uint4* dh = (uint4*)(smc + SMB_H(0));
        uint4* dl = (uint4*)(smc + SMB_L(0));
        dh[t] = sh[t]; dl[t] = sl[t];
        dh[t + 256] = sh[t + 256]; dl[t + 256] = sl[t + 256];
        if (t < 64) { dh[t + 512] = sh[t + 512]; dl[t + 512] = sl[t + 512]; }
        #pragma unroll 1
        for (int s = 0; s < 4; s++) {
            int p = gg * 4 + s;
            float4 sp = g_smp[pix0 + p];
            Pref P = issueGather(xb, sp, j);
            retireGather(P, smc + SMA_H(0) + p * BPITCH, smc + SMA_L(0) + p * BPITCH, j);
        }
    }
    __syncthreads();

    // ---- pipelined main loop ----
    #pragma unroll 1
    for (int k = 0; k < 9; k++) {
        int cur = k & 1, nxt = cur ^ 1;
        bool pre = (k < 8);
        u32 baseAH = sb + SMA_H(cur), baseAL = sb + SMA_L(cur);
        u32 baseBH = sb + SMB_H(cur), baseBL = sb + SMB_L(cur);
        char* rowHb = smc + SMA_H(nxt);
        char* rowLb = smc + SMA_L(nxt);
        uint4 bhp0, blp0, bhp1, blp1, bhp2, blp2;

        #pragma unroll
        for (int s = 0; s < 4; s++) {
            // --- issue prefetch for tap k+1 ---
            Pref P;
            int p = gg * 4 + s;
            if (pre) {
                if (s == 0) {
                    const uint4* shh = (const uint4*)(g_wth + (size_t)(k + 1) * OO * BPITCH);
                    const uint4* sll = (const uint4*)(g_wtl + (size_t)(k + 1) * OO * BPITCH);
                    bhp0 = shh[t];       blp0 = sll[t];
                    bhp1 = shh[t + 256]; blp1 = sll[t + 256];
                    if (t < 64) { bhp2 = shh[t + 512]; blp2 = sll[t + 512]; }
                }
                float4 sp = g_smp[(size_t)(k + 1) * NPIX + pix0 + p];
                P = issueGather(xb, sp, j);
            }

            // --- GEMM step ks = s on current buffers ---
            {
                u32 ah[2][4], al[2][4];
                #pragma unroll
                for (int mi = 0; mi < 2; mi++) {
                    ldsm4(ah[mi], baseAH + aOff[mi] + s * 32);
                    ldsm4(al[mi], baseAL + aOff[mi] + s * 32);
                }
                #pragma unroll
                for (int half = 0; half < 2; half++) {
                    u32 bh[4], bl[4];
                    ldsm4(bh, baseBH + bOff[half] + s * 32);
                    ldsm4(bl, baseBL + bOff[half] + s * 32);
                    #pragma unroll
                    for (int mi = 0; mi < 2; mi++) {
                        mma16816(acc[mi][2 * half],     ah[mi], bh[0], bh[1]);
                        mma16816(acc[mi][2 * half],     ah[mi], bl[0], bl[1]);
                        mma16816(acc[mi][2 * half],     al[mi], bh[0], bh[1]);
                        mma16816(acc[mi][2 * half + 1], ah[mi], bh[2], bh[3]);
                        mma16816(acc[mi][2 * half + 1], ah[mi], bl[2], bl[3]);
                        mma16816(acc[mi][2 * half + 1], al[mi], bh[2], bh[3]);
                    }
                }
            }

            // --- retire prefetch into next buffers ---
            if (pre) {
                retireGather(P, rowHb + p * BPITCH, rowLb + p * BPITCH, j);
                if (s == 0) {
                    uint4* dh = (uint4*)(smc + SMB_H(nxt));
                    uint4* dl = (uint4*)(smc + SMB_L(nxt));
                    dh[t] = bhp0; dl[t] = blp0;
                    dh[t + 256] = bhp1; dl[t + 256] = blp1;
                    if (t < 64) { dh[t + 512] = bhp2; dl[t + 512] = blp2; }
                }
            }
        }
        __syncthreads();
    }

    // ---- epilogue: fragment -> g_raw ----
    int er = lane >> 2, ec = (lane & 3) * 2;
    #pragma unroll
    for (int mi = 0; mi < 2; mi++) {
        #pragma unroll
        for (int ni = 0; ni < 4; ni++) {
            int pix = pix0 + mb + 16 * mi + er;
            int o = nb + 8 * ni + ec;
            *(float2*)(g_raw + (size_t)pix * OO + o)       = make_float2(acc[mi][ni][0], acc[mi][ni][1]);
            *(float2*)(g_raw + (size_t)(pix + 8) * OO + o) = make_float2(acc[mi][ni][2], acc[mi][ni][3]);
        }
    }

    // ---- fused BN partial stats (fixed-order shfl tree + fixed warp order) ----
    float ps[8], pq[8];
    #pragma unroll
    for (int ni = 0; ni < 4; ni++) {
        float s0 = 0.f, q0 = 0.f, s1 = 0.f, q1 = 0.f;
        #pragma unroll
        for (int mi = 0; mi < 2; mi++) {
            float a0 = acc[mi][ni][0], a1 = acc[mi][ni][1];
            float a2 = acc[mi][ni][2], a3 = acc[mi][ni][3];
            s0 += a0 + a2;  q0 += a0 * a0 + a2 * a2;
            s1 += a1 + a3;  q1 += a1 * a1 + a3 * a3;
        }
        ps[2 * ni] = s0; pq[2 * ni] = q0;
        ps[2 * ni + 1] = s1; pq[2 * ni + 1] = q1;
    }
    #pragma unroll
    for (int off = 4; off <= 16; off <<= 1) {
        #pragma unroll
        for (int i = 0; i < 8; i++) {
            ps[i] += __shfl_xor_sync(0xFFFFFFFF, ps[i], off);
            pq[i] += __shfl_xor_sync(0xFFFFFFFF, pq[i], off);
        }
    }
    float* sms = (float*)smc;          // [8][32]
    float* smq = sms + 256;            // [8][32]
    if (lane < 4) {
        #pragma unroll
        for (int ni = 0; ni < 4; ni++) {
            int lo = 8 * ni + lane * 2;
            sms[w * 32 + lo]     = ps[2 * ni];
            sms[w * 32 + lo + 1] = ps[2 * ni + 1];
            smq[w * 32 + lo]     = pq[2 * ni];
            smq[w * 32 + lo + 1] = pq[2 * ni + 1];
        }
    }
    __syncthreads();
    if (t < 64) {
        int grp = t >> 5, wo = t & 31;
        float S = sms[(grp * 4 + 0) * 32 + wo] + sms[(grp * 4 + 1) * 32 + wo]
                + sms[(grp * 4 + 2) * 32 + wo] + sms[(grp * 4 + 3) * 32 + wo];
        float Q = smq[(grp * 4 + 0) * 32 + wo] + smq[(grp * 4 + 1) * 32 + wo]
                + smq[(grp * 4 + 2) * 32 + wo] + smq[(grp * 4 + 3) * 32 + wo];
        g_psum[blockIdx.x * OO + t] = S;
        g_psq[blockIdx.x * OO + t]  = Q;
    }
}

// ---------------- K3: finalize stats -> scale/shift ----------------
__global__ void k_stats2(const float* __restrict__ gamma, const float* __restrict__ beta) {
    __shared__ float ss[256], sq[256];
    int ch = blockIdx.x, t = threadIdx.x;
    ss[t] = g_psum[t * OO + ch] + g_psum[(t + 256) * OO + ch];
    sq[t] = g_psq[t * OO + ch]  + g_psq[(t + 256) * OO + ch];
    __syncthreads();
    for (int s = 128; s > 0; s >>= 1) {
        if (t < s) { ss[t] += ss[t + s]; sq[t] += sq[t + s]; }
        __syncthreads();
    }
    if (t == 0) {
        const float inv_n = 1.0f / (float)NPIX;
        float mean = ss[0] * inv_n;
        float var  = sq[0] * inv_n - mean * mean;
        float inv  = rsqrtf(var + 1e-5f);
        float sc   = gamma[ch] * inv;
        g_scale[ch] = sc;
        g_shift[ch] = beta[ch] - mean * sc;
        // conv bias cancels exactly inside batch-norm (per-channel constant)
    }
}

// ---------------- K4: BN + ReLU + NHWC->NCHW ----------------
__global__ void k_bnout(float* __restrict__ out) {
    __shared__ float s[64][65];
    __shared__ float scs[64], shs[64];
    int t = threadIdx.x;
    if (t < 64) { scs[t] = g_scale[t]; shs[t] = g_shift[t]; }
    __syncthreads();
    int pix0 = blockIdx.x * 64;
    int b = pix0 >> 14;
    int pl = pix0 & 16383;
    #pragma unroll
    for (int j = 0; j < 4; j++) {
        int idx = t + j * 256;
        int p = idx >> 4;      // 0..63 local pixel
        int q = idx & 15;      // float4 group of channels
        float4 v = *(const float4*)(g_raw + (size_t)(pix0 + p) * OO + q * 4);
        int c = q * 4;
        s[c + 0][p] = fmaxf(fmaf(v.x, scs[c + 0], shs[c + 0]), 0.0f);
        s[c + 1][p] = fmaxf(fmaf(v.y, scs[c + 1], shs[c + 1]), 0.0f);
        s[c + 2][p] = fmaxf(fmaf(v.z, scs[c + 2], shs[c + 2]), 0.0f);
        s[c + 3][p] = fmaxf(fmaf(v.w, scs[c + 3], shs[c + 3]), 0.0f);
    }
    __syncthreads();
    #pragma unroll
    for (int j = 0; j < 4; j++) {
        int idx = t + j * 256;
        int o = idx >> 4;
        int q = idx & 15;
        float4 r = make_float4(s[o][q * 4], s[o][q * 4 + 1], s[o][q * 4 + 2], s[o][q * 4 + 3]);
        *(float4*)(out + (size_t)(b * OO + o) * HWP + pl + q * 4) = r;
    }
}

// ---------------- launch ----------------
extern "C" void kernel_launch(void* const* d_in, const int* in_sizes, int n_in,
                              void* d_out, int out_size) {
    const float* x     = (const float*)d_in[0];
    const float* ow    = (const float*)d_in[1];
    const float* ob    = (const float*)d_in[2];
    const float* wt    = (const float*)d_in[3];
    // d_in[4] = bias: cancels exactly in batch norm, unused
    const float* gamma = (const float*)d_in[5];
    const float* beta  = (const float*)d_in[6];
    float* out = (float*)d_out;

    cudaFuncSetAttribute(k_offset, cudaFuncAttributeMaxDynamicSharedMemorySize, 576 * 28 * 4);
    cudaFuncSetAttribute(k_main, cudaFuncAttributeMaxDynamicSharedMemorySize, SM_TOT);

    k_transpose<<<dim3(HWP / 32, CC / 32, BB), dim3(32, 8)>>>(x);
    k_prep<<<(9 * OO * CC + 255) / 256, 256>>>(wt, ow);
    k_offset<<<BB * HH / 2, 128, 576 * 28 * 4>>>(ob);
    k_main<<<NBLK, 256, SM_TOT>>>();
    k_stats2<<<64, 256>>>(gamma, beta);
    k_bnout<<<NPIX / 64, 256>>>(out);
}